// round 11
// baseline (speedup 1.0000x reference)
#include <cuda_runtime.h>
#include <cuda_fp16.h>
#include <mma.h>
#include <cstdint>

using namespace nvcuda;

// ---------------- problem constants ----------------
#define BATCH   256
#define INSTRS  64
#define TOKENS  16
#define HID     256
#define EMB     256
#define FOURH   1024
#define KTOT    512
#define NTOK    (BATCH*INSTRS)   // 16384

// ---------------- token kernel: full-N blocks ----------------
// BM=128 rows/block, all 1024 gate columns per block, grid = 128 blocks.
// A (x|h) resident in smem per step; W streamed in 64x128-half tiles, 3-stage ring.
#define BM    128
#define ALD   520                // A smem stride in halfs (512 + 8 pad; rows 1040B)
#define TNT   16                 // n-tiles of 64 gate-columns
#define TBK   128                // K per W tile (halfs)
#define WLD   136                // W stage stride in halfs (128 + 8)
#define WSTG_H (64*WLD)          // 8704 halfs per stage
#define CLD   68                 // epilogue Cs stride (floats)

// token smem layout (bytes):
//  A    @ 0      : 128*520*2      = 133120
//  W    @ 133120 : 3*64*136*2    = 52224
//  Cs   @ 185344 : 128*68*4      = 34816
//  Aidx @ 220160 : 512
//  Arow @ 220672 : 1024
#define T_W_OFF    133120
#define T_CS_OFF   185344
#define T_AIDX_OFF 220160
#define T_AROW_OFF 220672
#define SMEM_TOK   221696

// ---------------- instr kernel (round-5/10 proven: BN=64, BK=64, 2-stage) ----------------
#define IBN  64
#define IBK  64
#define LDSH 72
#define INK  (KTOT/IBK)          // 8
// smem: As[2][128*72]h=36864 @0 (Cs overlays), Bs[2][64*72]h=18432 @36864,
// Aidx @55296, Arow unused
#define SMEM_INS 56832

// ---------------- device state ----------------
// h ping-ponged by step parity: step t reads h[(t&1)^1], writes h[t&1].
__device__ __half g_h_tok[2][(size_t)NTOK * HID];
__device__ float  g_c_tok[(size_t)NTOK * HID];
__device__ __half g_h_ins[2][(size_t)BATCH * HID];
__device__ float  g_c_ins[(size_t)BATCH * HID];
__device__ __half g_instr_repr[(size_t)NTOK * HID];
__device__ int    g_perm_tok[NTOK];
__device__ int    g_cnt_tok[TOKENS];
__device__ int    g_perm_ins[BATCH];
__device__ int    g_cnt_ins[INSTRS];
// pre-converted fp16 operands
__device__ __half g_emb_h[(size_t)4096 * EMB];
__device__ __half g_W_tok[(size_t)FOURH * KTOT];   // [jp][512], gate-interleaved
__device__ __half g_W_ins[(size_t)FOURH * KTOT];

#define CP_ASYNC16(dst, src) \
    asm volatile("cp.async.cg.shared.global [%0], [%1], 16;" :: "r"(dst), "l"(src))
#define CP_COMMIT  asm volatile("cp.async.commit_group;")
#define CP_WAIT0   asm volatile("cp.async.wait_group 0;")
#define CP_WAIT1   asm volatile("cp.async.wait_group 1;")

// fast, accurate-enough sigmoid/tanh (validated: rel_err 9.1e-5)
__device__ __forceinline__ float fsig(float x) { return 1.0f / (1.0f + __expf(-x)); }
__device__ __forceinline__ float ftanh(float x) {
    x = fminf(fmaxf(x, -15.0f), 15.0f);
    float e = __expf(2.0f * x);
    return (e - 1.0f) / (e + 1.0f);
}

// ================= token phase: full-N block per step =================
__global__ void __launch_bounds__(256)
tok_step(int t, const int* __restrict__ tok,
         const float* __restrict__ bias, const int* __restrict__ ntok)
{
    const int m0 = blockIdx.x * BM;
    if (m0 >= g_cnt_tok[t]) return;

    extern __shared__ char smraw[];
    __half*        A    = (__half*)smraw;                  // [128][ALD]
    __half*        Wb   = (__half*)(smraw + T_W_OFF);      // [3][64][WLD]
    float*         Cs   = (float*)(smraw + T_CS_OFF);      // [128][CLD]
    int*           Aidx = (int*)(smraw + T_AIDX_OFF);
    const __half** Arow = (const __half**)(smraw + T_AROW_OFF);

    const int tid = threadIdx.x;
    const int wp  = t & 1;
    const int rp  = wp ^ 1;
    const __half* hbase = g_h_tok[rp];

    for (int r = tid; r < BM; r += 256) {
        int n = g_perm_tok[m0 + r];
        Aidx[r] = n;
        Arow[r] = g_emb_h + (size_t)__ldg(&tok[n * TOKENS + t]) * EMB;
    }
    __syncthreads();

    // ---- group 0: A tile (x half always, h half if t>0) ----
#pragma unroll
    for (int i = 0; i < 16; ++i) {
        int c  = tid + i * 256;          // 0..4095 chunks of 8 halfs
        int r  = c >> 5;                 // 32 chunks per row
        int cc = (c & 31) << 3;          // half index in [0,256)
        uint32_t dst = (uint32_t)__cvta_generic_to_shared(A + r * ALD + cc);
        CP_ASYNC16(dst, Arow[r] + cc);
    }
    if (t > 0) {
#pragma unroll
        for (int i = 0; i < 16; ++i) {
            int c  = tid + i * 256;
            int r  = c >> 5;
            int cc = (c & 31) << 3;
            uint32_t dst = (uint32_t)__cvta_generic_to_shared(A + r * ALD + 256 + cc);
            CP_ASYNC16(dst, hbase + (size_t)Aidx[r] * HID + cc);
        }
    }
    CP_COMMIT;

    const int KT    = (t == 0) ? 2 : 4;   // K-iters per n-tile (h half skipped at t=0)
    const int NTILE = TNT * KT;           // linear W-tile count

    auto issueW = [&](int it, int stage) {
        int nt = it / KT, kt = it - (it / KT) * KT;
        __half* Wd = Wb + stage * WSTG_H;
#pragma unroll
        for (int i = 0; i < 4; ++i) {
            int c  = tid + i * 256;       // 0..1023 chunks
            int r  = c >> 4;              // 16 chunks per row (128 halfs)
            int c8 = (c & 15) << 3;
            uint32_t dst = (uint32_t)__cvta_generic_to_shared(Wd + r * WLD + c8);
            CP_ASYNC16(dst, g_W_tok + (size_t)(nt * 64 + r) * KTOT + kt * TBK + c8);
        }
        CP_COMMIT;
    };
    issueW(0, 0);
    issueW(1, 1);

    const int warp = tid >> 5;
    const int wm   = warp >> 1;   // 0..3: 32-row slice
    const int wn   = warp & 1;    // 0..1: 32-col slice within the 64-wide n-tile

    wmma::fragment<wmma::accumulator, 16, 16, 16, float> cf[2][2];

    for (int it = 0; it < NTILE; ++it) {
        int nt = it / KT;
        int kt = it - nt * KT;

        if (kt == 0) {
#pragma unroll
            for (int mi = 0; mi < 2; ++mi)
#pragma unroll
                for (int ni = 0; ni < 2; ++ni)
                    wmma::fill_fragment(cf[mi][ni], 0.0f);
        }

        if (it == NTILE - 1) { CP_WAIT0; } else { CP_WAIT1; }
        __syncthreads();
        if (it + 2 < NTILE) issueW(it + 2, (it + 2) % 3);

        const __half* Ws = Wb + (it % 3) * WSTG_H;
        const __half* Ab = A + kt * TBK;
#pragma unroll
        for (int kk = 0; kk < TBK; kk += 16) {
            wmma::fragment<wmma::matrix_a, 16, 16, 16, __half, wmma::row_major> a[2];
            wmma::fragment<wmma::matrix_b, 16, 16, 16, __half, wmma::col_major> b[2];
#pragma unroll
            for (int mi = 0; mi < 2; ++mi)
                wmma::load_matrix_sync(a[mi], Ab + (wm * 32 + mi * 16) * ALD + kk, ALD);
#pragma unroll
            for (int ni = 0; ni < 2; ++ni)
                wmma::load_matrix_sync(b[ni], Ws + (wn * 32 + ni * 16) * WLD + kk, WLD);
#pragma unroll
            for (int mi = 0; mi < 2; ++mi)
#pragma unroll
                for (int ni = 0; ni < 2; ++ni)
                    wmma::mma_sync(cf[mi][ni], a[mi], b[ni], cf[mi][ni]);
        }

        if (kt == KT - 1) {
            // n-tile complete: stage gates, update h/c for d in [nt*16, nt*16+16)
#pragma unroll
            for (int mi = 0; mi < 2; ++mi)
#pragma unroll
                for (int ni = 0; ni < 2; ++ni)
                    wmma::store_matrix_sync(&Cs[(wm * 32 + mi * 16) * CLD + wn * 32 + ni * 16],
                                            cf[mi][ni], CLD, wmma::mem_row_major);
            __syncthreads();

            int r = tid >> 1;
            int n = Aidx[r];
            int L = __ldg(&ntok[n]);
            if (t < L) {
                __half* hp = g_h_tok[wp];
                float*  cp = g_c_tok;
                const bool last = (t == L - 1);
#pragma unroll
                for (int i = 0; i < 8; ++i) {
                    int dl = (tid & 1) * 8 + i;          // 0..15 local d
                    int dg = nt * 16 + dl;               // global d
                    float gi = Cs[r * CLD + dl * 4 + 0] + __ldg(&bias[dg]);
                    float gf = Cs[r * CLD + dl * 4 + 1] + __ldg(&bias[256 + dg]);
                    float gg = Cs[r * CLD + dl * 4 + 2] + __ldg(&bias[512 + dg]);
                    float go = Cs[r * CLD + dl * 4 + 3] + __ldg(&bias[768 + dg]);
                    float i_ = fsig(gi);
                    float f_ = fsig(gf);
                    float g_ = ftanh(gg);
                    float o_ = fsig(go);
                    size_t idx = (size_t)n * HID + dg;
                    float cn = f_ * cp[idx] + i_ * g_;
                    cp[idx] = cn;
                    __half hv = __float2half_rn(o_ * ftanh(cn));
                    hp[idx] = hv;
                    if (last) g_instr_repr[idx] = hv;    // fused gather
                }
            }
            // next iteration's top __syncthreads() protects Cs reuse
        }
    }
}

// ================= instr phase: proven round-5/10 kernel, 64 launches =================
__global__ void __launch_bounds__(256)
ins_step(int s, const float* __restrict__ bias, const int* __restrict__ ninstr)
{
    if (blockIdx.x * BM >= g_cnt_ins[s]) return;

    extern __shared__ char smraw[];
    __half* As   = (__half*)smraw;
    __half* Bs   = (__half*)(smraw + 36864);
    int*    Aidx = (int*)(smraw + 55296);
    float*  Cs   = (float*)smraw;   // overlay

    const int m0  = blockIdx.x * BM;
    const int n0  = blockIdx.y * IBN;
    const int tid = threadIdx.x;
    const int wp  = s & 1;
    const int rp  = wp ^ 1;

    const __half* hbase = g_h_ins[rp];

    for (int r = tid; r < BM; r += 256) Aidx[r] = g_perm_ins[m0 + r];
    __syncthreads();

    auto issue = [&](int kt, int buf) {
        __half* Ad = As + buf * BM * LDSH;
#pragma unroll
        for (int i = 0; i < 4; ++i) {
            int c  = tid + i * 256;
            int r  = c >> 3;
            int c8 = (c & 7) << 3;
            int n  = Aidx[r];
            const __half* src = (kt < 4)
                ? g_instr_repr + ((size_t)n * INSTRS + s) * HID + kt * IBK + c8
                : hbase + (size_t)n * HID + (kt - 4) * IBK + c8;
            uint32_t dst = (uint32_t)__cvta_generic_to_shared(Ad + r * LDSH + c8);
            CP_ASYNC16(dst, src);
        }
        __half* Bd = Bs + buf * IBN * LDSH;
#pragma unroll
        for (int i = 0; i < 2; ++i) {
            int c  = tid + i * 256;
            int r  = c >> 3;
            int c8 = (c & 7) << 3;
            const __half* src = g_W_ins + (size_t)(n0 + r) * KTOT + kt * IBK + c8;
            uint32_t dst = (uint32_t)__cvta_generic_to_shared(Bd + r * LDSH + c8);
            CP_ASYNC16(dst, src);
        }
        CP_COMMIT;
    };

    wmma::fragment<wmma::accumulator, 16, 16, 16, float> cf[2][2];
#pragma unroll
    for (int mi = 0; mi < 2; ++mi)
#pragma unroll
        for (int ni = 0; ni < 2; ++ni)
            wmma::fill_fragment(cf[mi][ni], 0.0f);

    const int warp = tid >> 5;
    const int wm   = warp >> 1;
    const int wn   = warp & 1;

    const int nk_eff = (s == 0) ? 4 : INK;   // h==0 at s=0

    issue(0, 0);
    for (int kt = 0; kt < nk_eff; ++kt) {
        CP_WAIT0;
        __syncthreads();
        if (kt + 1 < nk_eff) issue(kt + 1, (kt + 1) & 1);
        const __half* Ab = As + (kt & 1) * BM * LDSH;
        const __half* Bb = Bs + (kt & 1) * IBN * LDSH;
#pragma unroll
        for (int kk = 0; kk < IBK; kk += 16) {
            wmma::fragment<wmma::matrix_a, 16, 16, 16, __half, wmma::row_major> a[2];
            wmma::fragment<wmma::matrix_b, 16, 16, 16, __half, wmma::col_major> b[2];
#pragma unroll
            for (int mi = 0; mi < 2; ++mi)
                wmma::load_matrix_sync(a[mi], Ab + (wm * 32 + mi * 16) * LDSH + kk, LDSH);
#pragma unroll
            for (int ni = 0; ni < 2; ++ni)
                wmma::load_matrix_sync(b[ni], Bb + (wn * 32 + ni * 16) * LDSH + kk, LDSH);
#pragma unroll
            for (int mi = 0; mi < 2; ++mi)
#pragma unroll
                for (int ni = 0; ni < 2; ++ni)
                    wmma::mma_sync(cf[mi][ni], a[mi], b[ni], cf[mi][ni]);
        }
    }

    __syncthreads();
#pragma unroll
    for (int mi = 0; mi < 2; ++mi)
#pragma unroll
        for (int ni = 0; ni < 2; ++ni)
            wmma::store_matrix_sync(&Cs[(wm * 32 + mi * 16) * CLD + wn * 32 + ni * 16],
                                    cf[mi][ni], CLD, wmma::mem_row_major);
    __syncthreads();

    {
        int r = tid >> 1;
        int n = Aidx[r];
        int L = __ldg(&ninstr[n]);
        if (s < L) {
            __half* hp = g_h_ins[wp];
            float*  cp = g_c_ins;
            int dg0 = (n0 >> 2) + (tid & 1) * 8;
#pragma unroll
            for (int i = 0; i < 8; ++i) {
                int dl = (tid & 1) * 8 + i;
                int dg = dg0 + i;
                float gi = Cs[r * CLD + dl * 4 + 0] + __ldg(&bias[dg]);
                float gf = Cs[r * CLD + dl * 4 + 1] + __ldg(&bias[256 + dg]);
                float gg = Cs[r * CLD + dl * 4 + 2] + __ldg(&bias[512 + dg]);
                float go = Cs[r * CLD + dl * 4 + 3] + __ldg(&bias[768 + dg]);
                float i_ = fsig(gi);
                float f_ = fsig(gf);
                float g_ = ftanh(gg);
                float o_ = fsig(go);
                size_t idx = (size_t)n * HID + dg;
                float cn = f_ * cp[idx] + i_ * g_;
                cp[idx] = cn;
                hp[idx] = __float2half_rn(o_ * ftanh(cn));
            }
        }
    }
}

// merged prep: convert weights (gate-interleaved [jp][512]) + embedding to fp16
__global__ void __launch_bounds__(256)
prep_all(const float* __restrict__ WihT, const float* __restrict__ WhhT,
         const float* __restrict__ WihI, const float* __restrict__ WhhI,
         const float* __restrict__ emb)
{
    int idx = blockIdx.x * 256 + threadIdx.x;      // grid covers 4096*256
    g_emb_h[idx] = __float2half_rn(emb[idx]);
    if (idx < FOURH * KTOT) {
        int jp = idx >> 9;
        int k  = idx & 511;
        int j  = (jp & 3) * 256 + (jp >> 2);       // gate*256 + d
        float v = (k < 256) ? WihT[j * 256 + k] : WhhT[j * 256 + (k - 256)];
        g_W_tok[idx] = __float2half_rn(v);
        float u = (k < 256) ? WihI[j * 256 + k] : WhhI[j * 256 + (k - 256)];
        g_W_ins[idx] = __float2half_rn(u);
    }
}

// counting sort by length (descending) + active-count table
__global__ void build_perm(const int* __restrict__ ntok,
                           const int* __restrict__ ninstr)
{
    __shared__ int hist[65];
    __shared__ int off[65];
    if (blockIdx.x == 0) {
        for (int i = threadIdx.x; i < 17; i += blockDim.x) hist[i] = 0;
        __syncthreads();
        for (int i = threadIdx.x; i < NTOK; i += blockDim.x)
            atomicAdd(&hist[ntok[i]], 1);
        __syncthreads();
        if (threadIdx.x == 0) {
            int acc = 0;
            for (int l = 16; l >= 0; --l) { off[l] = acc; acc += hist[l]; }
            for (int t = 0; t < TOKENS; ++t) g_cnt_tok[t] = off[t];
        }
        __syncthreads();
        for (int i = threadIdx.x; i < NTOK; i += blockDim.x) {
            int p = atomicAdd(&off[ntok[i]], 1);
            g_perm_tok[p] = i;
        }
    } else {
        for (int i = threadIdx.x; i < 65; i += blockDim.x) hist[i] = 0;
        __syncthreads();
        for (int i = threadIdx.x; i < BATCH; i += blockDim.x)
            atomicAdd(&hist[ninstr[i]], 1);
        __syncthreads();
        if (threadIdx.x == 0) {
            int acc = 0;
            for (int l = 64; l >= 0; --l) { off[l] = acc; acc += hist[l]; }
            for (int s = 0; s < INSTRS; ++s) g_cnt_ins[s] = off[s];
        }
        __syncthreads();
        for (int i = threadIdx.x; i < BATCH; i += blockDim.x) {
            int p = atomicAdd(&off[ninstr[i]], 1);
            g_perm_ins[p] = i;
        }
    }
}

__global__ void __launch_bounds__(256) zero_state()
{
    int idx = blockIdx.x * 256 + threadIdx.x;   // grid covers NTOK*HID
    g_h_tok[0][idx] = __half(0.0f);
    g_h_tok[1][idx] = __half(0.0f);
    g_c_tok[idx]    = 0.0f;
    g_instr_repr[idx] = __half(0.0f);           // rows with len==0 keep zeros
    if (idx < BATCH * HID) {
        g_h_ins[0][idx] = __half(0.0f);
        g_h_ins[1][idx] = __half(0.0f);
        g_c_ins[idx]    = 0.0f;
    }
}

__global__ void __launch_bounds__(256)
final_linear(const int* __restrict__ ninstr,
             const float* __restrict__ linW,
             const float* __restrict__ linb,
             float* __restrict__ out)
{
    int b = blockIdx.x, tid = threadIdx.x;
    int L = ninstr[b];
    float h = (L > 0) ? __half2float(g_h_ins[(L - 1) & 1][(size_t)b * HID + tid]) : 0.0f;
    float v = h * linW[tid];
#pragma unroll
    for (int o = 16; o > 0; o >>= 1) v += __shfl_down_sync(0xffffffffu, v, o);
    __shared__ float red[8];
    if ((tid & 31) == 0) red[tid >> 5] = v;
    __syncthreads();
    if (tid < 8) {
        float s = red[tid];
#pragma unroll
        for (int o = 4; o > 0; o >>= 1) s += __shfl_down_sync(0xffu, s, o);
        if (tid == 0) out[b] = s + linb[0];
    }
}

extern "C" void kernel_launch(void* const* d_in, const int* in_sizes, int n_in,
                              void* d_out, int out_size)
{
    const int*   blocks = (const int*)d_in[0];
    const int*   ninstr = (const int*)d_in[1];
    const int*   ntok   = (const int*)d_in[2];
    const float* emb    = (const float*)d_in[3];
    const float* WihT   = (const float*)d_in[4];
    const float* WhhT   = (const float*)d_in[5];
    const float* bT     = (const float*)d_in[6];
    const float* WihI   = (const float*)d_in[7];
    const float* WhhI   = (const float*)d_in[8];
    const float* bI     = (const float*)d_in[9];
    const float* linW   = (const float*)d_in[10];
    const float* linb   = (const float*)d_in[11];
    float* out = (float*)d_out;
    (void)in_sizes; (void)n_in; (void)out_size;

    cudaFuncSetAttribute(tok_step, cudaFuncAttributeMaxDynamicSharedMemorySize, SMEM_TOK);
    cudaFuncSetAttribute(ins_step, cudaFuncAttributeMaxDynamicSharedMemorySize, SMEM_INS);

    zero_state<<<NTOK * HID / 256, 256>>>();
    build_perm<<<2, 512>>>(ntok, ninstr);
    prep_all<<<4096 * EMB / 256, 256>>>(WihT, WhhT, WihI, WhhI, emb);

    for (int t = 0; t < TOKENS; ++t) {
        tok_step<<<NTOK / BM, 256, SMEM_TOK>>>(t, blocks, bT, ntok);   // 128 blocks, self-trim
    }
    for (int s = 0; s < INSTRS; ++s) {
        dim3 grid(BATCH / BM, FOURH / IBN);        // 2 x 16
        ins_step<<<grid, 256, SMEM_INS>>>(s, bI, ninstr);
    }
    final_linear<<<BATCH, 256>>>(ninstr, linW, linb, out);
}

// round 13
// speedup vs baseline: 1.5335x; 1.5335x over previous
#include <cuda_runtime.h>
#include <cuda_fp16.h>
#include <mma.h>
#include <cstdint>

using namespace nvcuda;

// ---------------- problem constants ----------------
#define BATCH   256
#define INSTRS  64
#define TOKENS  16
#define HID     256
#define EMB     256
#define FOURH   1024
#define KTOT    512
#define NTOK    (BATCH*INSTRS)   // 16384

// ---------------- token GEMM config (round-5 proven: BK=64, BN=64, 2-stage) ----------------
#define BM 128
#define BN 64
#define BK 64
#define LDSH 72                  // BK + 8 pad
#define NK  (KTOT/BK)            // 8  (CONSTANT loop bound — fully unrolled)
#define CLD 68
#define SMEM_TOK 56832           // As[2] 36864 | Bs[2] 18432 @36864 | Aidx @55296 | Arow @55808

// ---------------- instr persistent kernel: 16 blocks x 16 rows, no grid sync ----------------
#define JB 16                    // rows per block
#define JALD 520                 // A stride (512 + 8) halfs
#define JWLD 136                 // W tile stride halfs (128 + 8)
#define JWSTG (256*JWLD)         // halfs per W stage (256 jp-cols x 128 K)
#define JCLD 260                 // Cs stride floats
// smem layout (bytes):
//  A    @ 0      : 16*520*2   = 16640   (x | h, h persistent across steps)
//  HN   @ 16640  : 16*256*2   = 8192    (staged new h)
//  CC   @ 24832  : 16*256*4   = 16384   (c state, fp32)
//  CS   @ 41216  : 16*260*4   = 16640   (gate staging)
//  W    @ 57856  : 2*34816*2  = 139264  (2-stage ring, distance-1 prefetch)
//  IDX  @ 197120 : 64,  LL @ 197184 : 64
#define J_HN_OFF  16640
#define J_CC_OFF  24832
#define J_CS_OFF  41216
#define J_W_OFF   57856
#define J_IDX_OFF 197120
#define J_LL_OFF  197184
#define SMEM_J    197248

// ---------------- device state ----------------
__device__ __half g_h_tok[2][(size_t)NTOK * HID];  // ping-pong by parity (token phase)
__device__ float  g_c_tok[(size_t)NTOK * HID];
__device__ __half g_instr_repr[(size_t)NTOK * HID];
__device__ __half g_hfin[(size_t)BATCH * HID];     // instr-phase final h per batch row
__device__ int    g_perm_tok[NTOK];
__device__ int    g_cnt_tok[TOKENS];
__device__ int    g_perm_ins[BATCH];
__device__ int    g_cnt_ins[INSTRS];
__device__ __half g_emb_h[(size_t)4096 * EMB];
__device__ __half g_W_tok[(size_t)FOURH * KTOT];   // [jp][512], gate-interleaved
__device__ __half g_W_ins[(size_t)FOURH * KTOT];

#define CP_ASYNC16(dst, src) \
    asm volatile("cp.async.cg.shared.global [%0], [%1], 16;" :: "r"(dst), "l"(src))
#define CP_COMMIT  asm volatile("cp.async.commit_group;")
#define CP_WAIT0   asm volatile("cp.async.wait_group 0;")

__device__ __forceinline__ float fsig(float x) { return 1.0f / (1.0f + __expf(-x)); }
__device__ __forceinline__ float ftanh(float x) {
    x = fminf(fmaxf(x, -15.0f), 15.0f);
    float e = __expf(2.0f * x);
    return (e - 1.0f) / (e + 1.0f);
}

// ================= token phase: round-5 proven kernel, per-step launches =================
__global__ void __launch_bounds__(256)
tok_step(int t, const int* __restrict__ tok,
         const float* __restrict__ bias, const int* __restrict__ ntok)
{
    if (blockIdx.x * BM >= g_cnt_tok[t]) return;

    extern __shared__ char smraw[];
    __half*        As   = (__half*)smraw;
    __half*        Bs   = (__half*)(smraw + 36864);
    int*           Aidx = (int*)(smraw + 55296);
    const __half** Arow = (const __half**)(smraw + 55808);
    float*         Cs   = (float*)smraw;   // overlay

    const int m0  = blockIdx.x * BM;
    const int n0  = blockIdx.y * BN;
    const int tid = threadIdx.x;
    const int wp  = t & 1;
    const int rp  = wp ^ 1;
    const __half* hbase = g_h_tok[rp];

    for (int r = tid; r < BM; r += 256) {
        int n = g_perm_tok[m0 + r];
        Aidx[r] = n;
        Arow[r] = g_emb_h + (size_t)__ldg(&tok[n * TOKENS + t]) * EMB;
    }
    __syncthreads();

    auto issue = [&](int kt, int buf) {
        __half* Ad = As + buf * BM * LDSH;
#pragma unroll
        for (int i = 0; i < 4; ++i) {
            int c  = tid + i * 256;
            int r  = c >> 3;
            int c8 = (c & 7) << 3;
            const __half* src = (kt < 4)
                ? Arow[r] + kt * BK + c8
                : hbase + (size_t)Aidx[r] * HID + (kt - 4) * BK + c8;
            uint32_t dst = (uint32_t)__cvta_generic_to_shared(Ad + r * LDSH + c8);
            CP_ASYNC16(dst, src);
        }
        __half* Bd = Bs + buf * BN * LDSH;
#pragma unroll
        for (int i = 0; i < 2; ++i) {
            int c  = tid + i * 256;
            int r  = c >> 3;
            int c8 = (c & 7) << 3;
            const __half* src = g_W_tok + (size_t)(n0 + r) * KTOT + kt * BK + c8;
            uint32_t dst = (uint32_t)__cvta_generic_to_shared(Bd + r * LDSH + c8);
            CP_ASYNC16(dst, src);
        }
        CP_COMMIT;
    };

    wmma::fragment<wmma::accumulator, 16, 16, 16, float> cf[2][2];
#pragma unroll
    for (int mi = 0; mi < 2; ++mi)
#pragma unroll
        for (int ni = 0; ni < 2; ++ni)
            wmma::fill_fragment(cf[mi][ni], 0.0f);

    const int warp = tid >> 5;
    const int wm   = warp >> 1;
    const int wn   = warp & 1;

    issue(0, 0);
#pragma unroll
    for (int kt = 0; kt < NK; ++kt) {
        CP_WAIT0;
        __syncthreads();
        if (kt + 1 < NK) issue(kt + 1, (kt + 1) & 1);
        const __half* Ab = As + (kt & 1) * BM * LDSH;
        const __half* Bb = Bs + (kt & 1) * BN * LDSH;
#pragma unroll
        for (int kk = 0; kk < BK; kk += 16) {
            wmma::fragment<wmma::matrix_a, 16, 16, 16, __half, wmma::row_major> a[2];
            wmma::fragment<wmma::matrix_b, 16, 16, 16, __half, wmma::col_major> b[2];
#pragma unroll
            for (int mi = 0; mi < 2; ++mi)
                wmma::load_matrix_sync(a[mi], Ab + (wm * 32 + mi * 16) * LDSH + kk, LDSH);
#pragma unroll
            for (int ni = 0; ni < 2; ++ni)
                wmma::load_matrix_sync(b[ni], Bb + (wn * 32 + ni * 16) * LDSH + kk, LDSH);
#pragma unroll
            for (int mi = 0; mi < 2; ++mi)
#pragma unroll
                for (int ni = 0; ni < 2; ++ni)
                    wmma::mma_sync(cf[mi][ni], a[mi], b[ni], cf[mi][ni]);
        }
    }

    __syncthreads();
#pragma unroll
    for (int mi = 0; mi < 2; ++mi)
#pragma unroll
        for (int ni = 0; ni < 2; ++ni)
            wmma::store_matrix_sync(&Cs[(wm * 32 + mi * 16) * CLD + wn * 32 + ni * 16],
                                    cf[mi][ni], CLD, wmma::mem_row_major);
    __syncthreads();

    {
        int r = tid >> 1;
        int n = Aidx[r];
        int L = __ldg(&ntok[n]);
        if (t < L) {
            __half* hp = g_h_tok[wp];
            float*  cp = g_c_tok;
            const bool last = (t == L - 1);
            int dg0 = (n0 >> 2) + (tid & 1) * 8;
#pragma unroll
            for (int i = 0; i < 8; ++i) {
                int dl = (tid & 1) * 8 + i;
                int dg = dg0 + i;
                float gi = Cs[r * CLD + dl * 4 + 0] + __ldg(&bias[dg]);
                float gf = Cs[r * CLD + dl * 4 + 1] + __ldg(&bias[256 + dg]);
                float gg = Cs[r * CLD + dl * 4 + 2] + __ldg(&bias[512 + dg]);
                float go = Cs[r * CLD + dl * 4 + 3] + __ldg(&bias[768 + dg]);
                float i_ = fsig(gi);
                float f_ = fsig(gf);
                float g_ = ftanh(gg);
                float o_ = fsig(go);
                size_t idx = (size_t)n * HID + dg;
                float cn = f_ * cp[idx] + i_ * g_;
                cp[idx] = cn;
                __half hv = __float2half_rn(o_ * ftanh(cn));
                hp[idx] = hv;
                if (last) g_instr_repr[idx] = hv;   // fused gather
            }
        }
    }
}

// ================= instr phase: ONE launch, 16 row-owning blocks, NO grid sync =================
// FIXED pipeline: distance-1 prefetch, issue AFTER the barrier (token-kernel pattern).
__global__ void __launch_bounds__(512)
ins_persist(const float* __restrict__ bias, const int* __restrict__ ninstr)
{
    extern __shared__ char sm[];
    __half* A  = (__half*)sm;                       // [16][JALD]  x | h
    __half* HN = (__half*)(sm + J_HN_OFF);          // [16][256]
    float*  CC = (float*)(sm + J_CC_OFF);           // [16][256]
    float*  CS = (float*)(sm + J_CS_OFF);           // [16][JCLD]
    __half* W  = (__half*)(sm + J_W_OFF);           // [2][JWSTG]
    int*    IDX = (int*)(sm + J_IDX_OFF);
    int*    LL  = (int*)(sm + J_LL_OFF);

    const int tid = threadIdx.x;
    const int m0  = blockIdx.x * JB;

    if (tid < JB) {
        int n = g_perm_ins[m0 + tid];
        IDX[tid] = n;
        LL[tid]  = __ldg(&ninstr[n]);
    }
    for (int i = tid; i < JB * 256; i += 512) {
        int r = i >> 8, cix = i & 255;
        CC[i] = 0.0f;
        A[r * JALD + 256 + cix] = __half(0.0f);     // h=0 at s=0
    }
    __syncthreads();
    const int Lmax = LL[0];                         // perm sorted desc -> block max
    if (Lmax == 0) return;                          // g_hfin pre-zeroed

    const int warp = tid >> 5;                      // 0..15; owns 16 jp-cols of the 256-wide tile

    auto issueW = [&](int it, int stage) {
        int nt = it >> 2, kt = it & 3;
        __half* Wd = W + stage * JWSTG;
#pragma unroll
        for (int i = 0; i < 8; ++i) {
            int c  = tid + i * 512;                 // 0..4095 chunks
            int r  = c >> 4;                        // 16 chunks/row
            int c8 = (c & 15) << 3;
            uint32_t dst = (uint32_t)__cvta_generic_to_shared(Wd + r * JWLD + c8);
            CP_ASYNC16(dst, g_W_ins + (size_t)(nt * 256 + r) * KTOT + kt * 128 + c8);
        }
        CP_COMMIT;
    };

    for (int s = 0; s < Lmax; ++s) {
        // x load for this step (1 chunk per thread) + first W tile
        {
            int r  = tid >> 5;
            int cc = (tid & 31) << 3;
            uint32_t dst = (uint32_t)__cvta_generic_to_shared(A + r * JALD + cc);
            CP_ASYNC16(dst, g_instr_repr + ((size_t)IDX[r] * INSTRS + s) * HID + cc);
        }
        CP_COMMIT;
        issueW(0, 0);

        wmma::fragment<wmma::accumulator, 16, 16, 16, float> cf;

        for (int it = 0; it < 16; ++it) {
            int nt = it >> 2, kt = it & 3;
            if (kt == 0) wmma::fill_fragment(cf, 0.0f);

            CP_WAIT0;                               // stage(it) + x complete
            __syncthreads();                        // all warps done reading stage(it+1)'s old data
            if (it + 1 < 16) issueW(it + 1, (it + 1) & 1);   // opposite stage — safe

            const __half* Ws = W + (it & 1) * JWSTG;
            const __half* Ab = A + kt * 128;
#pragma unroll
            for (int kk = 0; kk < 128; kk += 16) {
                wmma::fragment<wmma::matrix_a, 16, 16, 16, __half, wmma::row_major> a;
                wmma::fragment<wmma::matrix_b, 16, 16, 16, __half, wmma::col_major> b;
                wmma::load_matrix_sync(a, Ab + kk, JALD);
                wmma::load_matrix_sync(b, Ws + (warp * 16) * JWLD + kk, JWLD);
                wmma::mma_sync(cf, a, b, cf);
            }

            if (kt == 3) {
                wmma::store_matrix_sync(&CS[warp * 16], cf, JCLD, wmma::mem_row_major);
                __syncthreads();
                // epilogue for d in [nt*64, nt*64+64): 16 rows x 64 d = 1024 items
#pragma unroll
                for (int ii = 0; ii < 2; ++ii) {
                    int item = tid + ii * 512;
                    int r  = item >> 6;
                    int dl = item & 63;
                    if (s < LL[r]) {
                        int dg = nt * 64 + dl;
                        float gi = CS[r * JCLD + dl * 4 + 0] + __ldg(&bias[dg]);
                        float gf = CS[r * JCLD + dl * 4 + 1] + __ldg(&bias[256 + dg]);
                        float gg = CS[r * JCLD + dl * 4 + 2] + __ldg(&bias[512 + dg]);
                        float go = CS[r * JCLD + dl * 4 + 3] + __ldg(&bias[768 + dg]);
                        float i_ = fsig(gi);
                        float f_ = fsig(gf);
                        float g_ = ftanh(gg);
                        float o_ = fsig(go);
                        float cn = f_ * CC[r * 256 + dg] + i_ * g_;
                        CC[r * 256 + dg] = cn;
                        __half hv = __float2half_rn(o_ * ftanh(cn));
                        HN[r * 256 + dg] = hv;
                        if (s == LL[r] - 1)
                            g_hfin[(size_t)IDX[r] * HID + dg] = hv;
                    }
                }
            }
        }

        // commit new h into A (frozen rows keep old h)
        __syncthreads();
        for (int i = tid; i < JB * 256; i += 512) {
            int r = i >> 8, cix = i & 255;
            if (s < LL[r]) A[r * JALD + 256 + cix] = HN[i];
        }
        __syncthreads();
    }
}

// merged prep: convert weights (gate-interleaved [jp][512]) + embedding to fp16
__global__ void __launch_bounds__(256)
prep_all(const float* __restrict__ WihT, const float* __restrict__ WhhT,
         const float* __restrict__ WihI, const float* __restrict__ WhhI,
         const float* __restrict__ emb)
{
    int idx = blockIdx.x * 256 + threadIdx.x;      // grid covers 4096*256
    g_emb_h[idx] = __float2half_rn(emb[idx]);
    if (idx < FOURH * KTOT) {
        int jp = idx >> 9;
        int k  = idx & 511;
        int j  = (jp & 3) * 256 + (jp >> 2);       // gate*256 + d
        float v = (k < 256) ? WihT[j * 256 + k] : WhhT[j * 256 + (k - 256)];
        g_W_tok[idx] = __float2half_rn(v);
        float u = (k < 256) ? WihI[j * 256 + k] : WhhI[j * 256 + (k - 256)];
        g_W_ins[idx] = __float2half_rn(u);
    }
}

// counting sort by length (descending) + active-count table
__global__ void build_perm(const int* __restrict__ ntok,
                           const int* __restrict__ ninstr)
{
    __shared__ int hist[65];
    __shared__ int off[65];
    if (blockIdx.x == 0) {
        for (int i = threadIdx.x; i < 17; i += blockDim.x) hist[i] = 0;
        __syncthreads();
        for (int i = threadIdx.x; i < NTOK; i += blockDim.x)
            atomicAdd(&hist[ntok[i]], 1);
        __syncthreads();
        if (threadIdx.x == 0) {
            int acc = 0;
            for (int l = 16; l >= 0; --l) { off[l] = acc; acc += hist[l]; }
            for (int t = 0; t < TOKENS; ++t) g_cnt_tok[t] = off[t];
        }
        __syncthreads();
        for (int i = threadIdx.x; i < NTOK; i += blockDim.x) {
            int p = atomicAdd(&off[ntok[i]], 1);
            g_perm_tok[p] = i;
        }
    } else {
        for (int i = threadIdx.x; i < 65; i += blockDim.x) hist[i] = 0;
        __syncthreads();
        for (int i = threadIdx.x; i < BATCH; i += blockDim.x)
            atomicAdd(&hist[ninstr[i]], 1);
        __syncthreads();
        if (threadIdx.x == 0) {
            int acc = 0;
            for (int l = 64; l >= 0; --l) { off[l] = acc; acc += hist[l]; }
            for (int s = 0; s < INSTRS; ++s) g_cnt_ins[s] = off[s];
        }
        __syncthreads();
        for (int i = threadIdx.x; i < BATCH; i += blockDim.x) {
            int p = atomicAdd(&off[ninstr[i]], 1);
            g_perm_ins[p] = i;
        }
    }
}

__global__ void __launch_bounds__(256) zero_state()
{
    int idx = blockIdx.x * 256 + threadIdx.x;   // grid covers NTOK*HID
    g_h_tok[0][idx] = __half(0.0f);
    g_h_tok[1][idx] = __half(0.0f);
    g_c_tok[idx]    = 0.0f;
    g_instr_repr[idx] = __half(0.0f);           // rows with len==0 keep zeros
    if (idx < BATCH * HID) g_hfin[idx] = __half(0.0f);
}

__global__ void __launch_bounds__(256)
final_linear(const float* __restrict__ linW,
             const float* __restrict__ linb,
             float* __restrict__ out)
{
    int b = blockIdx.x, tid = threadIdx.x;
    float h = __half2float(g_hfin[(size_t)b * HID + tid]);
    float v = h * linW[tid];
#pragma unroll
    for (int o = 16; o > 0; o >>= 1) v += __shfl_down_sync(0xffffffffu, v, o);
    __shared__ float red[8];
    if ((tid & 31) == 0) red[tid >> 5] = v;
    __syncthreads();
    if (tid < 8) {
        float s = red[tid];
#pragma unroll
        for (int o = 4; o > 0; o >>= 1) s += __shfl_down_sync(0xffu, s, o);
        if (tid == 0) out[b] = s + linb[0];
    }
}

extern "C" void kernel_launch(void* const* d_in, const int* in_sizes, int n_in,
                              void* d_out, int out_size)
{
    const int*   blocks = (const int*)d_in[0];
    const int*   ninstr = (const int*)d_in[1];
    const int*   ntok   = (const int*)d_in[2];
    const float* emb    = (const float*)d_in[3];
    const float* WihT   = (const float*)d_in[4];
    const float* WhhT   = (const float*)d_in[5];
    const float* bT     = (const float*)d_in[6];
    const float* WihI   = (const float*)d_in[7];
    const float* WhhI   = (const float*)d_in[8];
    const float* bI     = (const float*)d_in[9];
    const float* linW   = (const float*)d_in[10];
    const float* linb   = (const float*)d_in[11];
    float* out = (float*)d_out;
    (void)in_sizes; (void)n_in; (void)out_size;

    cudaFuncSetAttribute(tok_step,    cudaFuncAttributeMaxDynamicSharedMemorySize, SMEM_TOK);
    cudaFuncSetAttribute(ins_persist, cudaFuncAttributeMaxDynamicSharedMemorySize, SMEM_J);

    zero_state<<<NTOK * HID / 256, 256>>>();
    build_perm<<<2, 512>>>(ntok, ninstr);
    prep_all<<<4096 * EMB / 256, 256>>>(WihT, WhhT, WihI, WhhI, emb);

    for (int t = 0; t < TOKENS; ++t) {
        dim3 grid(NTOK / BM, FOURH / BN);          // 128 x 16, blocks self-trim
        tok_step<<<grid, 256, SMEM_TOK>>>(t, blocks, bT, ntok);
    }
    ins_persist<<<BATCH / JB, 512, SMEM_J>>>(bI, ninstr);   // 16 blocks, one launch
    final_linear<<<BATCH, 256>>>(linW, linb, out);
}

// round 14
// speedup vs baseline: 2.3105x; 1.5067x over previous
#include <cuda_runtime.h>
#include <cuda_fp16.h>
#include <mma.h>
#include <cstdint>

using namespace nvcuda;

// ---------------- problem constants ----------------
#define BATCH   256
#define INSTRS  64
#define TOKENS  16
#define HID     256
#define EMB     256
#define FOURH   1024
#define KTOT    512
#define NTOK    (BATCH*INSTRS)   // 16384

// ---------------- GEMM tile config (round-5 proven: fp16 m16n16k16, BK=64) ----------------
#define BM 128
#define BN 64
#define BK 64
#define LDSH 72                  // BK + 8 pad
#define NK  (KTOT/BK)            // 8
#define CLD 68                   // epilogue Cs stride (floats)

// token kernel smem (R5 exact): As[2] 36864 @0 (Cs overlays), Bs[2] 18432 @36864,
// Aidx @55296, Arow @55808
#define SMEM_TOK 56832

// instr kernel smem (4-stage): As[4][128*72]h=73728 @0 (Cs overlays),
// Bs[4][64*72]h=36864 @73728, Aidx @110592, Arow @111104
#define I_BS_OFF   73728
#define I_AIDX_OFF 110592
#define I_AROW_OFF 111104
#define SMEM_INS   112128

// ---------------- device state ----------------
// h ping-ponged by step parity: step t reads h[(t&1)^1], writes h[t&1].
__device__ __half g_h_tok[2][(size_t)NTOK * HID];
__device__ float  g_c_tok[(size_t)NTOK * HID];
__device__ __half g_h_ins[2][(size_t)BATCH * HID];
__device__ float  g_c_ins[(size_t)BATCH * HID];
__device__ __half g_instr_repr[(size_t)NTOK * HID];
__device__ int    g_perm_tok[NTOK];
__device__ int    g_cnt_tok[TOKENS];
__device__ int    g_perm_ins[BATCH];
__device__ int    g_cnt_ins[INSTRS];
// pre-converted fp16 operands
__device__ __half g_emb_h[(size_t)4096 * EMB];
__device__ __half g_W_tok[(size_t)FOURH * KTOT];   // [jp][512], gate-interleaved
__device__ __half g_W_ins[(size_t)FOURH * KTOT];

#define CP_ASYNC16(dst, src) \
    asm volatile("cp.async.cg.shared.global [%0], [%1], 16;" :: "r"(dst), "l"(src))
#define CP_COMMIT  asm volatile("cp.async.commit_group;")
#define CP_WAIT0   asm volatile("cp.async.wait_group 0;")
#define CP_WAIT1   asm volatile("cp.async.wait_group 1;")
#define CP_WAIT2   asm volatile("cp.async.wait_group 2;")

// ================= token phase: ROUND-5 EXACT fused step =================
__global__ void __launch_bounds__(256)
tok_step(int t, const int* __restrict__ tok,
         const float* __restrict__ bias, const int* __restrict__ ntok)
{
    if (blockIdx.x * BM >= g_cnt_tok[t]) return;

    extern __shared__ char smraw[];
    __half*        As   = (__half*)smraw;
    __half*        Bs   = (__half*)(smraw + 36864);
    int*           Aidx = (int*)(smraw + 55296);
    const __half** Arow = (const __half**)(smraw + 55808);
    float*         Cs   = (float*)smraw;   // overlay

    const int m0  = blockIdx.x * BM;
    const int n0  = blockIdx.y * BN;
    const int tid = threadIdx.x;
    const int wp  = t & 1;
    const int rp  = wp ^ 1;
    const __half* hbase = g_h_tok[rp];

    for (int r = tid; r < BM; r += 256) {
        int n = g_perm_tok[m0 + r];
        Aidx[r] = n;
        Arow[r] = g_emb_h + (size_t)__ldg(&tok[n * TOKENS + t]) * EMB;
    }
    __syncthreads();

    auto issue = [&](int kt, int buf) {
        __half* Ad = As + buf * BM * LDSH;
#pragma unroll
        for (int i = 0; i < 4; ++i) {
            int c  = tid + i * 256;
            int r  = c >> 3;
            int c8 = (c & 7) << 3;
            const __half* src = (kt < 4)
                ? Arow[r] + kt * BK + c8
                : hbase + (size_t)Aidx[r] * HID + (kt - 4) * BK + c8;
            uint32_t dst = (uint32_t)__cvta_generic_to_shared(Ad + r * LDSH + c8);
            CP_ASYNC16(dst, src);
        }
        __half* Bd = Bs + buf * BN * LDSH;
#pragma unroll
        for (int i = 0; i < 2; ++i) {
            int c  = tid + i * 256;
            int r  = c >> 3;
            int c8 = (c & 7) << 3;
            const __half* src = g_W_tok + (size_t)(n0 + r) * KTOT + kt * BK + c8;
            uint32_t dst = (uint32_t)__cvta_generic_to_shared(Bd + r * LDSH + c8);
            CP_ASYNC16(dst, src);
        }
        CP_COMMIT;
    };

    wmma::fragment<wmma::accumulator, 16, 16, 16, float> cf[2][2];
#pragma unroll
    for (int mi = 0; mi < 2; ++mi)
#pragma unroll
        for (int ni = 0; ni < 2; ++ni)
            wmma::fill_fragment(cf[mi][ni], 0.0f);

    const int warp = tid >> 5;
    const int wm   = warp >> 1;
    const int wn   = warp & 1;

    issue(0, 0);
    for (int kt = 0; kt < NK; ++kt) {
        CP_WAIT0;
        __syncthreads();
        if (kt + 1 < NK) issue(kt + 1, (kt + 1) & 1);
        const __half* Ab = As + (kt & 1) * BM * LDSH;
        const __half* Bb = Bs + (kt & 1) * BN * LDSH;
#pragma unroll
        for (int kk = 0; kk < BK; kk += 16) {
            wmma::fragment<wmma::matrix_a, 16, 16, 16, __half, wmma::row_major> a[2];
            wmma::fragment<wmma::matrix_b, 16, 16, 16, __half, wmma::col_major> b[2];
#pragma unroll
            for (int mi = 0; mi < 2; ++mi)
                wmma::load_matrix_sync(a[mi], Ab + (wm * 32 + mi * 16) * LDSH + kk, LDSH);
#pragma unroll
            for (int ni = 0; ni < 2; ++ni)
                wmma::load_matrix_sync(b[ni], Bb + (wn * 32 + ni * 16) * LDSH + kk, LDSH);
#pragma unroll
            for (int mi = 0; mi < 2; ++mi)
#pragma unroll
                for (int ni = 0; ni < 2; ++ni)
                    wmma::mma_sync(cf[mi][ni], a[mi], b[ni], cf[mi][ni]);
        }
    }

    __syncthreads();
#pragma unroll
    for (int mi = 0; mi < 2; ++mi)
#pragma unroll
        for (int ni = 0; ni < 2; ++ni)
            wmma::store_matrix_sync(&Cs[(wm * 32 + mi * 16) * CLD + wn * 32 + ni * 16],
                                    cf[mi][ni], CLD, wmma::mem_row_major);
    __syncthreads();

    {
        int r = tid >> 1;
        int n = Aidx[r];
        int L = __ldg(&ntok[n]);
        if (t < L) {
            __half* hp = g_h_tok[wp];
            float*  cp = g_c_tok;
            int dg0 = (n0 >> 2) + (tid & 1) * 8;
#pragma unroll
            for (int i = 0; i < 8; ++i) {
                int dl = (tid & 1) * 8 + i;
                int dg = dg0 + i;
                float gi = Cs[r * CLD + dl * 4 + 0] + __ldg(&bias[dg]);
                float gf = Cs[r * CLD + dl * 4 + 1] + __ldg(&bias[256 + dg]);
                float gg = Cs[r * CLD + dl * 4 + 2] + __ldg(&bias[512 + dg]);
                float go = Cs[r * CLD + dl * 4 + 3] + __ldg(&bias[768 + dg]);
                float i_ = 1.0f / (1.0f + expf(-gi));
                float f_ = 1.0f / (1.0f + expf(-gf));
                float g_ = tanhf(gg);
                float o_ = 1.0f / (1.0f + expf(-go));
                size_t idx = (size_t)n * HID + dg;
                float cn = f_ * cp[idx] + i_ * g_;
                cp[idx] = cn;
                hp[idx] = __float2half_rn(o_ * tanhf(cn));
            }
        }
    }
}

// ================= instr phase: R5 structure + 4-STAGE cp.async pipeline =================
// 32 blocks = 1 CTA/SM: no cross-CTA hiding, so pipeline depth is the lever.
__global__ void __launch_bounds__(256)
ins_step(int s, const float* __restrict__ bias, const int* __restrict__ ninstr)
{
    if (blockIdx.x * BM >= g_cnt_ins[s]) return;

    extern __shared__ char smraw[];
    __half* As   = (__half*)smraw;                      // [4][BM*LDSH]
    __half* Bs   = (__half*)(smraw + I_BS_OFF);         // [4][BN*LDSH]
    int*    Aidx = (int*)(smraw + I_AIDX_OFF);
    float*  Cs   = (float*)smraw;                       // overlay

    const int m0  = blockIdx.x * BM;
    const int n0  = blockIdx.y * BN;
    const int tid = threadIdx.x;
    const int wp  = s & 1;
    const int rp  = wp ^ 1;
    const __half* hbase = g_h_ins[rp];

    for (int r = tid; r < BM; r += 256) Aidx[r] = g_perm_ins[m0 + r];
    __syncthreads();

    auto issue = [&](int kt, int buf) {
        __half* Ad = As + buf * BM * LDSH;
#pragma unroll
        for (int i = 0; i < 4; ++i) {
            int c  = tid + i * 256;
            int r  = c >> 3;
            int c8 = (c & 7) << 3;
            int n  = Aidx[r];
            const __half* src = (kt < 4)
                ? g_instr_repr + ((size_t)n * INSTRS + s) * HID + kt * BK + c8
                : hbase + (size_t)n * HID + (kt - 4) * BK + c8;
            uint32_t dst = (uint32_t)__cvta_generic_to_shared(Ad + r * LDSH + c8);
            CP_ASYNC16(dst, src);
        }
        __half* Bd = Bs + buf * BN * LDSH;
#pragma unroll
        for (int i = 0; i < 2; ++i) {
            int c  = tid + i * 256;
            int r  = c >> 3;
            int c8 = (c & 7) << 3;
            const __half* src = g_W_ins + (size_t)(n0 + r) * KTOT + kt * BK + c8;
            uint32_t dst = (uint32_t)__cvta_generic_to_shared(Bd + r * LDSH + c8);
            CP_ASYNC16(dst, src);
        }
        CP_COMMIT;
    };

    wmma::fragment<wmma::accumulator, 16, 16, 16, float> cf[2][2];
#pragma unroll
    for (int mi = 0; mi < 2; ++mi)
#pragma unroll
        for (int ni = 0; ni < 2; ++ni)
            wmma::fill_fragment(cf[mi][ni], 0.0f);

    const int warp = tid >> 5;
    const int wm   = warp >> 1;
    const int wn   = warp & 1;

    issue(0, 0);
    issue(1, 1);
    issue(2, 2);
    for (int kt = 0; kt < NK; ++kt) {
        // pending groups at this point: kt .. min(kt+2, NK-1)
        if (kt < NK - 2)      { CP_WAIT2; }     // 3 pending -> leave 2, kt done
        else if (kt == NK - 2){ CP_WAIT1; }     // 2 pending -> leave 1, kt done
        else                  { CP_WAIT0; }     // 1 pending -> drain
        __syncthreads();                         // everyone done reading stage (kt+3)%4 = (kt-1)%4
        if (kt + 3 < NK) issue(kt + 3, (kt + 3) & 3);
        const __half* Ab = As + (kt & 3) * BM * LDSH;
        const __half* Bb = Bs + (kt & 3) * BN * LDSH;
#pragma unroll
        for (int kk = 0; kk < BK; kk += 16) {
            wmma::fragment<wmma::matrix_a, 16, 16, 16, __half, wmma::row_major> a[2];
            wmma::fragment<wmma::matrix_b, 16, 16, 16, __half, wmma::col_major> b[2];
#pragma unroll
            for (int mi = 0; mi < 2; ++mi)
                wmma::load_matrix_sync(a[mi], Ab + (wm * 32 + mi * 16) * LDSH + kk, LDSH);
#pragma unroll
            for (int ni = 0; ni < 2; ++ni)
                wmma::load_matrix_sync(b[ni], Bb + (wn * 32 + ni * 16) * LDSH + kk, LDSH);
#pragma unroll
            for (int mi = 0; mi < 2; ++mi)
#pragma unroll
                for (int ni = 0; ni < 2; ++ni)
                    wmma::mma_sync(cf[mi][ni], a[mi], b[ni], cf[mi][ni]);
        }
    }

    __syncthreads();
#pragma unroll
    for (int mi = 0; mi < 2; ++mi)
#pragma unroll
        for (int ni = 0; ni < 2; ++ni)
            wmma::store_matrix_sync(&Cs[(wm * 32 + mi * 16) * CLD + wn * 32 + ni * 16],
                                    cf[mi][ni], CLD, wmma::mem_row_major);
    __syncthreads();

    {
        int r = tid >> 1;
        int n = Aidx[r];
        int L = __ldg(&ninstr[n]);
        if (s < L) {
            __half* hp = g_h_ins[wp];
            float*  cp = g_c_ins;
            int dg0 = (n0 >> 2) + (tid & 1) * 8;
#pragma unroll
            for (int i = 0; i < 8; ++i) {
                int dl = (tid & 1) * 8 + i;
                int dg = dg0 + i;
                float gi = Cs[r * CLD + dl * 4 + 0] + __ldg(&bias[dg]);
                float gf = Cs[r * CLD + dl * 4 + 1] + __ldg(&bias[256 + dg]);
                float gg = Cs[r * CLD + dl * 4 + 2] + __ldg(&bias[512 + dg]);
                float go = Cs[r * CLD + dl * 4 + 3] + __ldg(&bias[768 + dg]);
                float i_ = 1.0f / (1.0f + expf(-gi));
                float f_ = 1.0f / (1.0f + expf(-gf));
                float g_ = tanhf(gg);
                float o_ = 1.0f / (1.0f + expf(-go));
                size_t idx = (size_t)n * HID + dg;
                float cn = f_ * cp[idx] + i_ * g_;
                cp[idx] = cn;
                hp[idx] = __float2half_rn(o_ * tanhf(cn));
            }
        }
    }
}

// gather final token-phase h from the parity buffer of each row's last step
__global__ void __launch_bounds__(256)
gather_tok(const int* __restrict__ ntok)
{
    int idx = blockIdx.x * 256 + threadIdx.x;
    int n = idx >> 8;
    int L = ntok[n];
    g_instr_repr[idx] = (L > 0) ? g_h_tok[(L - 1) & 1][idx] : __half(0.0f);
}

// convert weights into gate-interleaved fp16 [jp][512]
__global__ void __launch_bounds__(256)
prep_weights(const float* __restrict__ WihT, const float* __restrict__ WhhT,
             const float* __restrict__ WihI, const float* __restrict__ WhhI)
{
    int idx = blockIdx.x * 256 + threadIdx.x;
    int jp = idx >> 9;
    int k  = idx & 511;
    int j  = (jp & 3) * 256 + (jp >> 2);
    float v = (k < 256) ? WihT[j * 256 + k] : WhhT[j * 256 + (k - 256)];
    g_W_tok[idx] = __float2half_rn(v);
    float u = (k < 256) ? WihI[j * 256 + k] : WhhI[j * 256 + (k - 256)];
    g_W_ins[idx] = __float2half_rn(u);
}

__global__ void __launch_bounds__(256)
prep_emb(const float* __restrict__ emb)
{
    int idx = blockIdx.x * 256 + threadIdx.x;
    g_emb_h[idx] = __float2half_rn(emb[idx]);
}

// counting sort by length (descending) + active-count table
__global__ void build_perm(const int* __restrict__ ntok,
                           const int* __restrict__ ninstr)
{
    __shared__ int hist[65];
    __shared__ int off[65];
    if (blockIdx.x == 0) {
        for (int i = threadIdx.x; i < 17; i += blockDim.x) hist[i] = 0;
        __syncthreads();
        for (int i = threadIdx.x; i < NTOK; i += blockDim.x)
            atomicAdd(&hist[ntok[i]], 1);
        __syncthreads();
        if (threadIdx.x == 0) {
            int acc = 0;
            for (int l = 16; l >= 0; --l) { off[l] = acc; acc += hist[l]; }
            for (int t = 0; t < TOKENS; ++t) g_cnt_tok[t] = off[t];
        }
        __syncthreads();
        for (int i = threadIdx.x; i < NTOK; i += blockDim.x) {
            int p = atomicAdd(&off[ntok[i]], 1);
            g_perm_tok[p] = i;
        }
    } else {
        for (int i = threadIdx.x; i < 65; i += blockDim.x) hist[i] = 0;
        __syncthreads();
        for (int i = threadIdx.x; i < BATCH; i += blockDim.x)
            atomicAdd(&hist[ninstr[i]], 1);
        __syncthreads();
        if (threadIdx.x == 0) {
            int acc = 0;
            for (int l = 64; l >= 0; --l) { off[l] = acc; acc += hist[l]; }
            for (int s = 0; s < INSTRS; ++s) g_cnt_ins[s] = off[s];
        }
        __syncthreads();
        for (int i = threadIdx.x; i < BATCH; i += blockDim.x) {
            int p = atomicAdd(&off[ninstr[i]], 1);
            g_perm_ins[p] = i;
        }
    }
}

__global__ void __launch_bounds__(256) zero_state()
{
    int idx = blockIdx.x * 256 + threadIdx.x;
    g_h_tok[0][idx] = __half(0.0f);
    g_h_tok[1][idx] = __half(0.0f);
    g_c_tok[idx]    = 0.0f;
    if (idx < BATCH * HID) {
        g_h_ins[0][idx] = __half(0.0f);
        g_h_ins[1][idx] = __half(0.0f);
        g_c_ins[idx]    = 0.0f;
    }
}

__global__ void __launch_bounds__(256)
final_linear(const int* __restrict__ ninstr,
             const float* __restrict__ linW,
             const float* __restrict__ linb,
             float* __restrict__ out)
{
    int b = blockIdx.x, tid = threadIdx.x;
    int L = ninstr[b];
    float h = (L > 0) ? __half2float(g_h_ins[(L - 1) & 1][(size_t)b * HID + tid]) : 0.0f;
    float v = h * linW[tid];
#pragma unroll
    for (int o = 16; o > 0; o >>= 1) v += __shfl_down_sync(0xffffffffu, v, o);
    __shared__ float red[8];
    if ((tid & 31) == 0) red[tid >> 5] = v;
    __syncthreads();
    if (tid < 8) {
        float s = red[tid];
#pragma unroll
        for (int o = 4; o > 0; o >>= 1) s += __shfl_down_sync(0xffu, s, o);
        if (tid == 0) out[b] = s + linb[0];
    }
}

extern "C" void kernel_launch(void* const* d_in, const int* in_sizes, int n_in,
                              void* d_out, int out_size)
{
    const int*   blocks = (const int*)d_in[0];
    const int*   ninstr = (const int*)d_in[1];
    const int*   ntok   = (const int*)d_in[2];
    const float* emb    = (const float*)d_in[3];
    const float* WihT   = (const float*)d_in[4];
    const float* WhhT   = (const float*)d_in[5];
    const float* bT     = (const float*)d_in[6];
    const float* WihI   = (const float*)d_in[7];
    const float* WhhI   = (const float*)d_in[8];
    const float* bI     = (const float*)d_in[9];
    const float* linW   = (const float*)d_in[10];
    const float* linb   = (const float*)d_in[11];
    float* out = (float*)d_out;
    (void)in_sizes; (void)n_in; (void)out_size;

    cudaFuncSetAttribute(tok_step, cudaFuncAttributeMaxDynamicSharedMemorySize, SMEM_TOK);
    cudaFuncSetAttribute(ins_step, cudaFuncAttributeMaxDynamicSharedMemorySize, SMEM_INS);

    zero_state<<<NTOK * HID / 256, 256>>>();
    build_perm<<<2, 512>>>(ntok, ninstr);
    prep_weights<<<FOURH * KTOT / 256, 256>>>(WihT, WhhT, WihI, WhhI);
    prep_emb<<<4096 * EMB / 256, 256>>>(emb);

    for (int t = 0; t < TOKENS; ++t) {
        dim3 grid(NTOK / BM, FOURH / BN);          // 128 x 16, blocks self-trim
        tok_step<<<grid, 256, SMEM_TOK>>>(t, blocks, bT, ntok);
    }
    gather_tok<<<NTOK * HID / 256, 256>>>(ntok);
    for (int s = 0; s < INSTRS; ++s) {
        dim3 grid(BATCH / BM, FOURH / BN);         // 2 x 16
        ins_step<<<grid, 256, SMEM_INS>>>(s, bI, ninstr);
    }
    final_linear<<<BATCH, 256>>>(ninstr, linW, linb, out);
}

// round 15
// speedup vs baseline: 2.6116x; 1.1303x over previous
#include <cuda_runtime.h>
#include <cuda_fp16.h>
#include <mma.h>
#include <cstdint>

using namespace nvcuda;

// ---------------- problem constants ----------------
#define BATCH   256
#define INSTRS  64
#define TOKENS  16
#define HID     256
#define EMB     256
#define FOURH   1024
#define KTOT    512
#define NTOK    (BATCH*INSTRS)   // 16384

// ---------------- token GEMM (round-5 exact): BM=128, BN=64, BK=64, 2-stage ----------------
#define BM 128
#define BN 64
#define BK 64
#define LDSH 72                  // BK + 8 pad
#define NK  (KTOT/BK)            // 8
#define CLD 68                   // token epilogue Cs stride (floats)
#define SMEM_TOK 56832           // As[2] 36864 @0 (Cs overlay) | Bs[2] 18432 @36864 | Aidx @55296 | Arow @55808

// ---------------- instr GEMM: BN=32 (64 blocks -> halved per-block MMA issue) ----------------
#define IBN 32
#define ICLD 36                  // instr epilogue Cs stride (floats)
// smem: As[2][128*72]h = 36864 @0 (Cs 128*36*4=18432 overlays), Bs[2][32*72]h = 9216 @36864,
// Aidx @46080
#define I_BS_OFF   36864
#define I_AIDX_OFF 46080
#define SMEM_INS   46592

// ---------------- device state ----------------
// h ping-ponged by step parity: step t reads h[(t&1)^1], writes h[t&1].
__device__ __half g_h_tok[2][(size_t)NTOK * HID];
__device__ float  g_c_tok[(size_t)NTOK * HID];
__device__ __half g_h_ins[2][(size_t)BATCH * HID];
__device__ float  g_c_ins[(size_t)BATCH * HID];
__device__ __half g_instr_repr[(size_t)NTOK * HID];
__device__ int    g_perm_tok[NTOK];
__device__ int    g_cnt_tok[TOKENS];
__device__ int    g_perm_ins[BATCH];
__device__ int    g_cnt_ins[INSTRS];
// pre-converted fp16 operands
__device__ __half g_emb_h[(size_t)4096 * EMB];
__device__ __half g_W_tok[(size_t)FOURH * KTOT];   // [jp][512], gate-interleaved
__device__ __half g_W_ins[(size_t)FOURH * KTOT];

#define CP_ASYNC16(dst, src) \
    asm volatile("cp.async.cg.shared.global [%0], [%1], 16;" :: "r"(dst), "l"(src))
#define CP_COMMIT  asm volatile("cp.async.commit_group;")
#define CP_WAIT0   asm volatile("cp.async.wait_group 0;")

// ================= token phase: ROUND-5 body; FIRST -> compile-time NK=4 (h==0) =================
template<bool FIRST>
__global__ void __launch_bounds__(256)
tok_step(int t, const int* __restrict__ tok,
         const float* __restrict__ bias, const int* __restrict__ ntok)
{
    if (blockIdx.x * BM >= g_cnt_tok[t]) return;

    constexpr int NKE = FIRST ? 4 : NK;

    extern __shared__ char smraw[];
    __half*        As   = (__half*)smraw;
    __half*        Bs   = (__half*)(smraw + 36864);
    int*           Aidx = (int*)(smraw + 55296);
    const __half** Arow = (const __half**)(smraw + 55808);
    float*         Cs   = (float*)smraw;   // overlay

    const int m0  = blockIdx.x * BM;
    const int n0  = blockIdx.y * BN;
    const int tid = threadIdx.x;
    const int wp  = t & 1;
    const int rp  = wp ^ 1;
    const __half* hbase = g_h_tok[rp];

    for (int r = tid; r < BM; r += 256) {
        int n = g_perm_tok[m0 + r];
        Aidx[r] = n;
        Arow[r] = g_emb_h + (size_t)__ldg(&tok[n * TOKENS + t]) * EMB;
    }
    __syncthreads();

    auto issue = [&](int kt, int buf) {
        __half* Ad = As + buf * BM * LDSH;
#pragma unroll
        for (int i = 0; i < 4; ++i) {
            int c  = tid + i * 256;
            int r  = c >> 3;
            int c8 = (c & 7) << 3;
            const __half* src = (FIRST || kt < 4)
                ? Arow[r] + kt * BK + c8
                : hbase + (size_t)Aidx[r] * HID + (kt - 4) * BK + c8;
            uint32_t dst = (uint32_t)__cvta_generic_to_shared(Ad + r * LDSH + c8);
            CP_ASYNC16(dst, src);
        }
        __half* Bd = Bs + buf * BN * LDSH;
#pragma unroll
        for (int i = 0; i < 2; ++i) {
            int c  = tid + i * 256;
            int r  = c >> 3;
            int c8 = (c & 7) << 3;
            const __half* src = g_W_tok + (size_t)(n0 + r) * KTOT + kt * BK + c8;
            uint32_t dst = (uint32_t)__cvta_generic_to_shared(Bd + r * LDSH + c8);
            CP_ASYNC16(dst, src);
        }
        CP_COMMIT;
    };

    wmma::fragment<wmma::accumulator, 16, 16, 16, float> cf[2][2];
#pragma unroll
    for (int mi = 0; mi < 2; ++mi)
#pragma unroll
        for (int ni = 0; ni < 2; ++ni)
            wmma::fill_fragment(cf[mi][ni], 0.0f);

    const int warp = tid >> 5;
    const int wm   = warp >> 1;
    const int wn   = warp & 1;

    issue(0, 0);
    for (int kt = 0; kt < NKE; ++kt) {
        CP_WAIT0;
        __syncthreads();
        if (kt + 1 < NKE) issue(kt + 1, (kt + 1) & 1);
        const __half* Ab = As + (kt & 1) * BM * LDSH;
        const __half* Bb = Bs + (kt & 1) * BN * LDSH;
#pragma unroll
        for (int kk = 0; kk < BK; kk += 16) {
            wmma::fragment<wmma::matrix_a, 16, 16, 16, __half, wmma::row_major> a[2];
            wmma::fragment<wmma::matrix_b, 16, 16, 16, __half, wmma::col_major> b[2];
#pragma unroll
            for (int mi = 0; mi < 2; ++mi)
                wmma::load_matrix_sync(a[mi], Ab + (wm * 32 + mi * 16) * LDSH + kk, LDSH);
#pragma unroll
            for (int ni = 0; ni < 2; ++ni)
                wmma::load_matrix_sync(b[ni], Bb + (wn * 32 + ni * 16) * LDSH + kk, LDSH);
#pragma unroll
            for (int mi = 0; mi < 2; ++mi)
#pragma unroll
                for (int ni = 0; ni < 2; ++ni)
                    wmma::mma_sync(cf[mi][ni], a[mi], b[ni], cf[mi][ni]);
        }
    }

    __syncthreads();
#pragma unroll
    for (int mi = 0; mi < 2; ++mi)
#pragma unroll
        for (int ni = 0; ni < 2; ++ni)
            wmma::store_matrix_sync(&Cs[(wm * 32 + mi * 16) * CLD + wn * 32 + ni * 16],
                                    cf[mi][ni], CLD, wmma::mem_row_major);
    __syncthreads();

    {
        int r = tid >> 1;
        int n = Aidx[r];
        int L = __ldg(&ntok[n]);
        if (t < L) {
            __half* hp = g_h_tok[wp];
            float*  cp = g_c_tok;
            int dg0 = (n0 >> 2) + (tid & 1) * 8;
#pragma unroll
            for (int i = 0; i < 8; ++i) {
                int dl = (tid & 1) * 8 + i;
                int dg = dg0 + i;
                float gi = Cs[r * CLD + dl * 4 + 0] + __ldg(&bias[dg]);
                float gf = Cs[r * CLD + dl * 4 + 1] + __ldg(&bias[256 + dg]);
                float gg = Cs[r * CLD + dl * 4 + 2] + __ldg(&bias[512 + dg]);
                float go = Cs[r * CLD + dl * 4 + 3] + __ldg(&bias[768 + dg]);
                float i_ = 1.0f / (1.0f + expf(-gi));
                float f_ = 1.0f / (1.0f + expf(-gf));
                float g_ = tanhf(gg);
                float o_ = 1.0f / (1.0f + expf(-go));
                size_t idx = (size_t)n * HID + dg;
                float cn = f_ * cp[idx] + i_ * g_;
                cp[idx] = cn;
                hp[idx] = __float2half_rn(o_ * tanhf(cn));
            }
        }
    }
}

// ================= instr phase: BN=32 (64 blocks), warp tile 32x16, 2-stage =================
template<bool FIRST>
__global__ void __launch_bounds__(256)
ins_step(int s, const float* __restrict__ bias, const int* __restrict__ ninstr)
{
    if (blockIdx.x * BM >= g_cnt_ins[s]) return;

    constexpr int NKE = FIRST ? 4 : NK;

    extern __shared__ char smraw[];
    __half* As   = (__half*)smraw;                      // [2][BM*LDSH]
    __half* Bs   = (__half*)(smraw + I_BS_OFF);         // [2][IBN*LDSH]
    int*    Aidx = (int*)(smraw + I_AIDX_OFF);
    float*  Cs   = (float*)smraw;                       // overlay [128][ICLD]

    const int m0  = blockIdx.x * BM;
    const int n0  = blockIdx.y * IBN;
    const int tid = threadIdx.x;
    const int wp  = s & 1;
    const int rp  = wp ^ 1;
    const __half* hbase = g_h_ins[rp];

    for (int r = tid; r < BM; r += 256) Aidx[r] = g_perm_ins[m0 + r];
    __syncthreads();

    auto issue = [&](int kt, int buf) {
        __half* Ad = As + buf * BM * LDSH;
#pragma unroll
        for (int i = 0; i < 4; ++i) {
            int c  = tid + i * 256;
            int r  = c >> 3;
            int c8 = (c & 7) << 3;
            int n  = Aidx[r];
            const __half* src = (FIRST || kt < 4)
                ? g_instr_repr + ((size_t)n * INSTRS + s) * HID + kt * BK + c8
                : hbase + (size_t)n * HID + (kt - 4) * BK + c8;
            uint32_t dst = (uint32_t)__cvta_generic_to_shared(Ad + r * LDSH + c8);
            CP_ASYNC16(dst, src);
        }
        __half* Bd = Bs + buf * IBN * LDSH;
        {
            int c  = tid;                    // 256 chunks exactly: 32 rows x 8 chunks
            int r  = c >> 3;
            int c8 = (c & 7) << 3;
            const __half* src = g_W_ins + (size_t)(n0 + r) * KTOT + kt * BK + c8;
            uint32_t dst = (uint32_t)__cvta_generic_to_shared(Bd + r * LDSH + c8);
            CP_ASYNC16(dst, src);
        }
        CP_COMMIT;
    };

    wmma::fragment<wmma::accumulator, 16, 16, 16, float> cf[2];
#pragma unroll
    for (int mi = 0; mi < 2; ++mi)
        wmma::fill_fragment(cf[mi], 0.0f);

    const int warp = tid >> 5;
    const int wm   = warp >> 1;    // 0..3: 32-row slice
    const int wn   = warp & 1;     // 0..1: 16-col slice

    issue(0, 0);
    for (int kt = 0; kt < NKE; ++kt) {
        CP_WAIT0;
        __syncthreads();
        if (kt + 1 < NKE) issue(kt + 1, (kt + 1) & 1);
        const __half* Ab = As + (kt & 1) * BM * LDSH;
        const __half* Bb = Bs + (kt & 1) * IBN * LDSH;
#pragma unroll
        for (int kk = 0; kk < BK; kk += 16) {
            wmma::fragment<wmma::matrix_a, 16, 16, 16, __half, wmma::row_major> a[2];
            wmma::fragment<wmma::matrix_b, 16, 16, 16, __half, wmma::col_major> b;
#pragma unroll
            for (int mi = 0; mi < 2; ++mi)
                wmma::load_matrix_sync(a[mi], Ab + (wm * 32 + mi * 16) * LDSH + kk, LDSH);
            wmma::load_matrix_sync(b, Bb + (wn * 16) * LDSH + kk, LDSH);
#pragma unroll
            for (int mi = 0; mi < 2; ++mi)
                wmma::mma_sync(cf[mi], a[mi], b, cf[mi]);
        }
    }

    __syncthreads();
#pragma unroll
    for (int mi = 0; mi < 2; ++mi)
        wmma::store_matrix_sync(&Cs[(wm * 32 + mi * 16) * ICLD + wn * 16],
                                cf[mi], ICLD, wmma::mem_row_major);
    __syncthreads();

    {
        int r = tid >> 1;                   // 2 threads per row, 4 d's each
        int n = Aidx[r];
        int L = __ldg(&ninstr[n]);
        if (s < L) {
            __half* hp = g_h_ins[wp];
            float*  cp = g_c_ins;
            int dbase = n0 >> 2;            // 8 d's per block
#pragma unroll
            for (int i = 0; i < 4; ++i) {
                int dl = (tid & 1) * 4 + i; // 0..7
                int dg = dbase + dl;
                float gi = Cs[r * ICLD + dl * 4 + 0] + __ldg(&bias[dg]);
                float gf = Cs[r * ICLD + dl * 4 + 1] + __ldg(&bias[256 + dg]);
                float gg = Cs[r * ICLD + dl * 4 + 2] + __ldg(&bias[512 + dg]);
                float go = Cs[r * ICLD + dl * 4 + 3] + __ldg(&bias[768 + dg]);
                float i_ = 1.0f / (1.0f + expf(-gi));
                float f_ = 1.0f / (1.0f + expf(-gf));
                float g_ = tanhf(gg);
                float o_ = 1.0f / (1.0f + expf(-go));
                size_t idx = (size_t)n * HID + dg;
                float cn = f_ * cp[idx] + i_ * g_;
                cp[idx] = cn;
                hp[idx] = __float2half_rn(o_ * tanhf(cn));
            }
        }
    }
}

// gather final token-phase h from the parity buffer of each row's last step
__global__ void __launch_bounds__(256)
gather_tok(const int* __restrict__ ntok)
{
    int idx = blockIdx.x * 256 + threadIdx.x;
    int n = idx >> 8;
    int L = ntok[n];
    g_instr_repr[idx] = (L > 0) ? g_h_tok[(L - 1) & 1][idx] : __half(0.0f);
}

// merged prep: weights (gate-interleaved [jp][512]) + embedding -> fp16
__global__ void __launch_bounds__(256)
prep_all(const float* __restrict__ WihT, const float* __restrict__ WhhT,
         const float* __restrict__ WihI, const float* __restrict__ WhhI,
         const float* __restrict__ emb)
{
    int idx = blockIdx.x * 256 + threadIdx.x;      // grid covers 4096*256
    g_emb_h[idx] = __float2half_rn(emb[idx]);
    if (idx < FOURH * KTOT) {
        int jp = idx >> 9;
        int k  = idx & 511;
        int j  = (jp & 3) * 256 + (jp >> 2);
        float v = (k < 256) ? WihT[j * 256 + k] : WhhT[j * 256 + (k - 256)];
        g_W_tok[idx] = __float2half_rn(v);
        float u = (k < 256) ? WihI[j * 256 + k] : WhhI[j * 256 + (k - 256)];
        g_W_ins[idx] = __float2half_rn(u);
    }
}

// counting sort by length (descending) + active-count table
__global__ void build_perm(const int* __restrict__ ntok,
                           const int* __restrict__ ninstr)
{
    __shared__ int hist[65];
    __shared__ int off[65];
    if (blockIdx.x == 0) {
        for (int i = threadIdx.x; i < 17; i += blockDim.x) hist[i] = 0;
        __syncthreads();
        for (int i = threadIdx.x; i < NTOK; i += blockDim.x)
            atomicAdd(&hist[ntok[i]], 1);
        __syncthreads();
        if (threadIdx.x == 0) {
            int acc = 0;
            for (int l = 16; l >= 0; --l) { off[l] = acc; acc += hist[l]; }
            for (int t = 0; t < TOKENS; ++t) g_cnt_tok[t] = off[t];
        }
        __syncthreads();
        for (int i = threadIdx.x; i < NTOK; i += blockDim.x) {
            int p = atomicAdd(&off[ntok[i]], 1);
            g_perm_tok[p] = i;
        }
    } else {
        for (int i = threadIdx.x; i < 65; i += blockDim.x) hist[i] = 0;
        __syncthreads();
        for (int i = threadIdx.x; i < BATCH; i += blockDim.x)
            atomicAdd(&hist[ninstr[i]], 1);
        __syncthreads();
        if (threadIdx.x == 0) {
            int acc = 0;
            for (int l = 64; l >= 0; --l) { off[l] = acc; acc += hist[l]; }
            for (int s = 0; s < INSTRS; ++s) g_cnt_ins[s] = off[s];
        }
        __syncthreads();
        for (int i = threadIdx.x; i < BATCH; i += blockDim.x) {
            int p = atomicAdd(&off[ninstr[i]], 1);
            g_perm_ins[p] = i;
        }
    }
}

__global__ void __launch_bounds__(256) zero_state()
{
    int idx = blockIdx.x * 256 + threadIdx.x;   // grid covers NTOK*HID
    g_h_tok[0][idx] = __half(0.0f);
    g_h_tok[1][idx] = __half(0.0f);
    g_c_tok[idx]    = 0.0f;
    if (idx < BATCH * HID) {
        g_h_ins[0][idx] = __half(0.0f);
        g_h_ins[1][idx] = __half(0.0f);
        g_c_ins[idx]    = 0.0f;
    }
}

__global__ void __launch_bounds__(256)
final_linear(const int* __restrict__ ninstr,
             const float* __restrict__ linW,
             const float* __restrict__ linb,
             float* __restrict__ out)
{
    int b = blockIdx.x, tid = threadIdx.x;
    int L = ninstr[b];
    float h = (L > 0) ? __half2float(g_h_ins[(L - 1) & 1][(size_t)b * HID + tid]) : 0.0f;
    float v = h * linW[tid];
#pragma unroll
    for (int o = 16; o > 0; o >>= 1) v += __shfl_down_sync(0xffffffffu, v, o);
    __shared__ float red[8];
    if ((tid & 31) == 0) red[tid >> 5] = v;
    __syncthreads();
    if (tid < 8) {
        float s = red[tid];
#pragma unroll
        for (int o = 4; o > 0; o >>= 1) s += __shfl_down_sync(0xffu, s, o);
        if (tid == 0) out[b] = s + linb[0];
    }
}

extern "C" void kernel_launch(void* const* d_in, const int* in_sizes, int n_in,
                              void* d_out, int out_size)
{
    const int*   blocks = (const int*)d_in[0];
    const int*   ninstr = (const int*)d_in[1];
    const int*   ntok   = (const int*)d_in[2];
    const float* emb    = (const float*)d_in[3];
    const float* WihT   = (const float*)d_in[4];
    const float* WhhT   = (const float*)d_in[5];
    const float* bT     = (const float*)d_in[6];
    const float* WihI   = (const float*)d_in[7];
    const float* WhhI   = (const float*)d_in[8];
    const float* bI     = (const float*)d_in[9];
    const float* linW   = (const float*)d_in[10];
    const float* linb   = (const float*)d_in[11];
    float* out = (float*)d_out;
    (void)in_sizes; (void)n_in; (void)out_size;

    cudaFuncSetAttribute(tok_step<true>,  cudaFuncAttributeMaxDynamicSharedMemorySize, SMEM_TOK);
    cudaFuncSetAttribute(tok_step<false>, cudaFuncAttributeMaxDynamicSharedMemorySize, SMEM_TOK);
    cudaFuncSetAttribute(ins_step<true>,  cudaFuncAttributeMaxDynamicSharedMemorySize, SMEM_INS);
    cudaFuncSetAttribute(ins_step<false>, cudaFuncAttributeMaxDynamicSharedMemorySize, SMEM_INS);

    zero_state<<<NTOK * HID / 256, 256>>>();
    build_perm<<<2, 512>>>(ntok, ninstr);
    prep_all<<<4096 * EMB / 256, 256>>>(WihT, WhhT, WihI, WhhI, emb);

    {
        dim3 grid(NTOK / BM, FOURH / BN);              // 128 x 16
        tok_step<true><<<grid, 256, SMEM_TOK>>>(0, blocks, bT, ntok);
        for (int t = 1; t < TOKENS; ++t)
            tok_step<false><<<grid, 256, SMEM_TOK>>>(t, blocks, bT, ntok);
    }
    gather_tok<<<NTOK * HID / 256, 256>>>(ntok);
    {
        dim3 grid(BATCH / BM, FOURH / IBN);            // 2 x 32
        ins_step<true><<<grid, 256, SMEM_INS>>>(0, bI, ninstr);
        for (int s = 1; s < INSTRS; ++s)
            ins_step<false><<<grid, 256, SMEM_INS>>>(s, bI, ninstr);
    }
    final_linear<<<BATCH, 256>>>(ninstr, linW, linb, out);
}

// round 16
// speedup vs baseline: 2.7785x; 1.0639x over previous
#include <cuda_runtime.h>
#include <cuda_fp16.h>
#include <mma.h>
#include <cstdint>

using namespace nvcuda;

// ---------------- problem constants ----------------
#define BATCH   256
#define INSTRS  64
#define TOKENS  16
#define HID     256
#define EMB     256
#define FOURH   1024
#define KTOT    512
#define NTOK    (BATCH*INSTRS)   // 16384

// ---------------- token GEMM: BM=64, BN=64, BK=64, 2-stage (more CTAs/SM) ----------------
#define TBM 64
#define BN  64
#define BK  64
#define LDSH 72                  // BK + 8 pad
#define NK  (KTOT/BK)            // 8
#define CLD 68                   // token epilogue Cs stride (floats)
// smem: As[2][64*72]h = 18432 @0 (Cs [64][68]f = 17408 overlays),
//       Bs[2][64*72]h = 18432 @18432, Aidx @36864, Arow @37120
#define T_BS_OFF   18432
#define T_AIDX_OFF 36864
#define T_AROW_OFF 37120
#define SMEM_TOK   37632

// ---------------- instr GEMM: BM=128, IBN=16 (128 blocks), 2-stage ----------------
#define IBM 128
#define IBN 16
#define ICLD 20                  // instr epilogue Cs stride (floats)
// smem: As[2][128*72]h = 36864 @0 (Cs [128][20]f = 10240 overlays),
//       Bs[2][16*72]h = 4608 @36864, Aidx @41472
#define I_BS_OFF   36864
#define I_AIDX_OFF 41472
#define SMEM_INS   41984

// ---------------- device state ----------------
// h ping-ponged by step parity: step t reads h[(t&1)^1], writes h[t&1].
__device__ __half g_h_tok[2][(size_t)NTOK * HID];
__device__ float  g_c_tok[(size_t)NTOK * HID];
__device__ __half g_h_ins[2][(size_t)BATCH * HID];
__device__ float  g_c_ins[(size_t)BATCH * HID];
__device__ __half g_instr_repr[(size_t)NTOK * HID];
__device__ int    g_perm_tok[NTOK];
__device__ int    g_cnt_tok[TOKENS];
__device__ int    g_perm_ins[BATCH];
__device__ int    g_cnt_ins[INSTRS];
// pre-converted fp16 operands
__device__ __half g_emb_h[(size_t)4096 * EMB];
__device__ __half g_W_tok[(size_t)FOURH * KTOT];   // [jp][512], gate-interleaved
__device__ __half g_W_ins[(size_t)FOURH * KTOT];

#define CP_ASYNC16(dst, src) \
    asm volatile("cp.async.cg.shared.global [%0], [%1], 16;" :: "r"(dst), "l"(src))
#define CP_COMMIT  asm volatile("cp.async.commit_group;")
#define CP_WAIT0   asm volatile("cp.async.wait_group 0;")

// ================= token phase: BM=64 blocks, warp tile 16x32 =================
template<bool FIRST>
__global__ void __launch_bounds__(256)
tok_step(int t, const int* __restrict__ tok,
         const float* __restrict__ bias, const int* __restrict__ ntok)
{
    if (blockIdx.x * TBM >= g_cnt_tok[t]) return;

    constexpr int NKE = FIRST ? 4 : NK;

    extern __shared__ char smraw[];
    __half*        As   = (__half*)smraw;                    // [2][64*LDSH]
    __half*        Bs   = (__half*)(smraw + T_BS_OFF);       // [2][64*LDSH]
    int*           Aidx = (int*)(smraw + T_AIDX_OFF);
    const __half** Arow = (const __half**)(smraw + T_AROW_OFF);
    float*         Cs   = (float*)smraw;                     // overlay [64][CLD]

    const int m0  = blockIdx.x * TBM;
    const int n0  = blockIdx.y * BN;
    const int tid = threadIdx.x;
    const int wp  = t & 1;
    const int rp  = wp ^ 1;
    const __half* hbase = g_h_tok[rp];

    if (tid < TBM) {
        int n = g_perm_tok[m0 + tid];
        Aidx[tid] = n;
        Arow[tid] = g_emb_h + (size_t)__ldg(&tok[n * TOKENS + t]) * EMB;
    }
    __syncthreads();

    auto issue = [&](int kt, int buf) {
        __half* Ad = As + buf * TBM * LDSH;
        // A tile: 64x64 half = 512 chunks, 2/thread
#pragma unroll
        for (int i = 0; i < 2; ++i) {
            int c  = tid + i * 256;
            int r  = c >> 3;
            int c8 = (c & 7) << 3;
            const __half* src = (FIRST || kt < 4)
                ? Arow[r] + kt * BK + c8
                : hbase + (size_t)Aidx[r] * HID + (kt - 4) * BK + c8;
            uint32_t dst = (uint32_t)__cvta_generic_to_shared(Ad + r * LDSH + c8);
            CP_ASYNC16(dst, src);
        }
        __half* Bd = Bs + buf * BN * LDSH;
        // B tile: 64x64 half = 512 chunks, 2/thread
#pragma unroll
        for (int i = 0; i < 2; ++i) {
            int c  = tid + i * 256;
            int r  = c >> 3;
            int c8 = (c & 7) << 3;
            const __half* src = g_W_tok + (size_t)(n0 + r) * KTOT + kt * BK + c8;
            uint32_t dst = (uint32_t)__cvta_generic_to_shared(Bd + r * LDSH + c8);
            CP_ASYNC16(dst, src);
        }
        CP_COMMIT;
    };

    wmma::fragment<wmma::accumulator, 16, 16, 16, float> cf[2];
#pragma unroll
    for (int ni = 0; ni < 2; ++ni)
        wmma::fill_fragment(cf[ni], 0.0f);

    const int warp = tid >> 5;
    const int wm   = warp >> 1;   // 0..3: 16-row slice
    const int wn   = warp & 1;    // 0..1: 32-col slice

    issue(0, 0);
    for (int kt = 0; kt < NKE; ++kt) {
        CP_WAIT0;
        __syncthreads();
        if (kt + 1 < NKE) issue(kt + 1, (kt + 1) & 1);
        const __half* Ab = As + (kt & 1) * TBM * LDSH;
        const __half* Bb = Bs + (kt & 1) * BN * LDSH;
#pragma unroll
        for (int kk = 0; kk < BK; kk += 16) {
            wmma::fragment<wmma::matrix_a, 16, 16, 16, __half, wmma::row_major> a;
            wmma::fragment<wmma::matrix_b, 16, 16, 16, __half, wmma::col_major> b[2];
            wmma::load_matrix_sync(a, Ab + (wm * 16) * LDSH + kk, LDSH);
#pragma unroll
            for (int ni = 0; ni < 2; ++ni)
                wmma::load_matrix_sync(b[ni], Bb + (wn * 32 + ni * 16) * LDSH + kk, LDSH);
#pragma unroll
            for (int ni = 0; ni < 2; ++ni)
                wmma::mma_sync(cf[ni], a, b[ni], cf[ni]);
        }
    }

    __syncthreads();
#pragma unroll
    for (int ni = 0; ni < 2; ++ni)
        wmma::store_matrix_sync(&Cs[(wm * 16) * CLD + wn * 32 + ni * 16],
                                cf[ni], CLD, wmma::mem_row_major);
    __syncthreads();

    {
        int r = tid >> 2;                  // 64 rows, 4 threads/row
        int n = Aidx[r];
        int L = __ldg(&ntok[n]);
        if (t < L) {
            __half* hp = g_h_tok[wp];
            float*  cp = g_c_tok;
            int dg0 = (n0 >> 2) + (tid & 3) * 4;
#pragma unroll
            for (int i = 0; i < 4; ++i) {
                int dl = (tid & 3) * 4 + i;
                int dg = dg0 + i;
                float gi = Cs[r * CLD + dl * 4 + 0] + __ldg(&bias[dg]);
                float gf = Cs[r * CLD + dl * 4 + 1] + __ldg(&bias[256 + dg]);
                float gg = Cs[r * CLD + dl * 4 + 2] + __ldg(&bias[512 + dg]);
                float go = Cs[r * CLD + dl * 4 + 3] + __ldg(&bias[768 + dg]);
                float i_ = 1.0f / (1.0f + expf(-gi));
                float f_ = 1.0f / (1.0f + expf(-gf));
                float g_ = tanhf(gg);
                float o_ = 1.0f / (1.0f + expf(-go));
                size_t idx = (size_t)n * HID + dg;
                float cn = f_ * cp[idx] + i_ * g_;
                cp[idx] = cn;
                hp[idx] = __float2half_rn(o_ * tanhf(cn));
            }
        }
    }
}

// ================= instr phase: IBN=16 (128 blocks), warp tile 16x16 =================
template<bool FIRST>
__global__ void __launch_bounds__(256)
ins_step(int s, const float* __restrict__ bias, const int* __restrict__ ninstr)
{
    if (blockIdx.x * IBM >= g_cnt_ins[s]) return;

    constexpr int NKE = FIRST ? 4 : NK;

    extern __shared__ char smraw[];
    __half* As   = (__half*)smraw;                      // [2][IBM*LDSH]
    __half* Bs   = (__half*)(smraw + I_BS_OFF);         // [2][IBN*LDSH]
    int*    Aidx = (int*)(smraw + I_AIDX_OFF);
    float*  Cs   = (float*)smraw;                       // overlay [128][ICLD]

    const int m0  = blockIdx.x * IBM;
    const int n0  = blockIdx.y * IBN;
    const int tid = threadIdx.x;
    const int wp  = s & 1;
    const int rp  = wp ^ 1;
    const __half* hbase = g_h_ins[rp];

    for (int r = tid; r < IBM; r += 256) Aidx[r] = g_perm_ins[m0 + r];
    __syncthreads();

    auto issue = [&](int kt, int buf) {
        __half* Ad = As + buf * IBM * LDSH;
#pragma unroll
        for (int i = 0; i < 4; ++i) {
            int c  = tid + i * 256;
            int r  = c >> 3;
            int c8 = (c & 7) << 3;
            int n  = Aidx[r];
            const __half* src = (FIRST || kt < 4)
                ? g_instr_repr + ((size_t)n * INSTRS + s) * HID + kt * BK + c8
                : hbase + (size_t)n * HID + (kt - 4) * BK + c8;
            uint32_t dst = (uint32_t)__cvta_generic_to_shared(Ad + r * LDSH + c8);
            CP_ASYNC16(dst, src);
        }
        __half* Bd = Bs + buf * IBN * LDSH;
        if (tid < 128) {                 // 16 rows x 8 chunks = 128 chunks
            int r  = tid >> 3;
            int c8 = (tid & 7) << 3;
            const __half* src = g_W_ins + (size_t)(n0 + r) * KTOT + kt * BK + c8;
            uint32_t dst = (uint32_t)__cvta_generic_to_shared(Bd + r * LDSH + c8);
            CP_ASYNC16(dst, src);
        }
        CP_COMMIT;
    };

    wmma::fragment<wmma::accumulator, 16, 16, 16, float> cf;
    wmma::fill_fragment(cf, 0.0f);

    const int warp = tid >> 5;          // 0..7: 16-row slice; single 16-col n tile

    issue(0, 0);
    for (int kt = 0; kt < NKE; ++kt) {
        CP_WAIT0;
        __syncthreads();
        if (kt + 1 < NKE) issue(kt + 1, (kt + 1) & 1);
        const __half* Ab = As + (kt & 1) * IBM * LDSH;
        const __half* Bb = Bs + (kt & 1) * IBN * LDSH;
#pragma unroll
        for (int kk = 0; kk < BK; kk += 16) {
            wmma::fragment<wmma::matrix_a, 16, 16, 16, __half, wmma::row_major> a;
            wmma::fragment<wmma::matrix_b, 16, 16, 16, __half, wmma::col_major> b;
            wmma::load_matrix_sync(a, Ab + (warp * 16) * LDSH + kk, LDSH);
            wmma::load_matrix_sync(b, Bb + kk, LDSH);
            wmma::mma_sync(cf, a, b, cf);
        }
    }

    __syncthreads();
    wmma::store_matrix_sync(&Cs[(warp * 16) * ICLD], cf, ICLD, wmma::mem_row_major);
    __syncthreads();

    {
        int r = tid >> 1;                 // 128 rows, 2 threads/row, 2 d's each
        int n = Aidx[r];
        int L = __ldg(&ninstr[n]);
        if (s < L) {
            __half* hp = g_h_ins[wp];
            float*  cp = g_c_ins;
            int dbase = n0 >> 2;          // 4 d's per block
#pragma unroll
            for (int i = 0; i < 2; ++i) {
                int dl = (tid & 1) * 2 + i;   // 0..3
                int dg = dbase + dl;
                float gi = Cs[r * ICLD + dl * 4 + 0] + __ldg(&bias[dg]);
                float gf = Cs[r * ICLD + dl * 4 + 1] + __ldg(&bias[256 + dg]);
                float gg = Cs[r * ICLD + dl * 4 + 2] + __ldg(&bias[512 + dg]);
                float go = Cs[r * ICLD + dl * 4 + 3] + __ldg(&bias[768 + dg]);
                float i_ = 1.0f / (1.0f + expf(-gi));
                float f_ = 1.0f / (1.0f + expf(-gf));
                float g_ = tanhf(gg);
                float o_ = 1.0f / (1.0f + expf(-go));
                size_t idx = (size_t)n * HID + dg;
                float cn = f_ * cp[idx] + i_ * g_;
                cp[idx] = cn;
                hp[idx] = __float2half_rn(o_ * tanhf(cn));
            }
        }
    }
}

// gather final token-phase h from the parity buffer of each row's last step
__global__ void __launch_bounds__(256)
gather_tok(const int* __restrict__ ntok)
{
    int idx = blockIdx.x * 256 + threadIdx.x;
    int n = idx >> 8;
    int L = ntok[n];
    g_instr_repr[idx] = (L > 0) ? g_h_tok[(L - 1) & 1][idx] : __half(0.0f);
}

// merged prep: weights (gate-interleaved [jp][512]) + embedding -> fp16
__global__ void __launch_bounds__(256)
prep_all(const float* __restrict__ WihT, const float* __restrict__ WhhT,
         const float* __restrict__ WihI, const float* __restrict__ WhhI,
         const float* __restrict__ emb)
{
    int idx = blockIdx.x * 256 + threadIdx.x;      // grid covers 4096*256
    g_emb_h[idx] = __float2half_rn(emb[idx]);
    if (idx < FOURH * KTOT) {
        int jp = idx >> 9;
        int k  = idx & 511;
        int j  = (jp & 3) * 256 + (jp >> 2);
        float v = (k < 256) ? WihT[j * 256 + k] : WhhT[j * 256 + (k - 256)];
        g_W_tok[idx] = __float2half_rn(v);
        float u = (k < 256) ? WihI[j * 256 + k] : WhhI[j * 256 + (k - 256)];
        g_W_ins[idx] = __float2half_rn(u);
    }
}

// counting sort by length (descending) + active-count table
__global__ void build_perm(const int* __restrict__ ntok,
                           const int* __restrict__ ninstr)
{
    __shared__ int hist[65];
    __shared__ int off[65];
    if (blockIdx.x == 0) {
        for (int i = threadIdx.x; i < 17; i += blockDim.x) hist[i] = 0;
        __syncthreads();
        for (int i = threadIdx.x; i < NTOK; i += blockDim.x)
            atomicAdd(&hist[ntok[i]], 1);
        __syncthreads();
        if (threadIdx.x == 0) {
            int acc = 0;
            for (int l = 16; l >= 0; --l) { off[l] = acc; acc += hist[l]; }
            for (int t = 0; t < TOKENS; ++t) g_cnt_tok[t] = off[t];
        }
        __syncthreads();
        for (int i = threadIdx.x; i < NTOK; i += blockDim.x) {
            int p = atomicAdd(&off[ntok[i]], 1);
            g_perm_tok[p] = i;
        }
    } else {
        for (int i = threadIdx.x; i < 65; i += blockDim.x) hist[i] = 0;
        __syncthreads();
        for (int i = threadIdx.x; i < BATCH; i += blockDim.x)
            atomicAdd(&hist[ninstr[i]], 1);
        __syncthreads();
        if (threadIdx.x == 0) {
            int acc = 0;
            for (int l = 64; l >= 0; --l) { off[l] = acc; acc += hist[l]; }
            for (int s = 0; s < INSTRS; ++s) g_cnt_ins[s] = off[s];
        }
        __syncthreads();
        for (int i = threadIdx.x; i < BATCH; i += blockDim.x) {
            int p = atomicAdd(&off[ninstr[i]], 1);
            g_perm_ins[p] = i;
        }
    }
}

__global__ void __launch_bounds__(256) zero_state()
{
    int idx = blockIdx.x * 256 + threadIdx.x;   // grid covers NTOK*HID
    g_h_tok[0][idx] = __half(0.0f);
    g_h_tok[1][idx] = __half(0.0f);
    g_c_tok[idx]    = 0.0f;
    if (idx < BATCH * HID) {
        g_h_ins[0][idx] = __half(0.0f);
        g_h_ins[1][idx] = __half(0.0f);
        g_c_ins[idx]    = 0.0f;
    }
}

__global__ void __launch_bounds__(256)
final_linear(const int* __restrict__ ninstr,
             const float* __restrict__ linW,
             const float* __restrict__ linb,
             float* __restrict__ out)
{
    int b = blockIdx.x, tid = threadIdx.x;
    int L = ninstr[b];
    float h = (L > 0) ? __half2float(g_h_ins[(L - 1) & 1][(size_t)b * HID + tid]) : 0.0f;
    float v = h * linW[tid];
#pragma unroll
    for (int o = 16; o > 0; o >>= 1) v += __shfl_down_sync(0xffffffffu, v, o);
    __shared__ float red[8];
    if ((tid & 31) == 0) red[tid >> 5] = v;
    __syncthreads();
    if (tid < 8) {
        float s = red[tid];
#pragma unroll
        for (int o = 4; o > 0; o >>= 1) s += __shfl_down_sync(0xffu, s, o);
        if (tid == 0) out[b] = s + linb[0];
    }
}

extern "C" void kernel_launch(void* const* d_in, const int* in_sizes, int n_in,
                              void* d_out, int out_size)
{
    const int*   blocks = (const int*)d_in[0];
    const int*   ninstr = (const int*)d_in[1];
    const int*   ntok   = (const int*)d_in[2];
    const float* emb    = (const float*)d_in[3];
    const float* WihT   = (const float*)d_in[4];
    const float* WhhT   = (const float*)d_in[5];
    const float* bT     = (const float*)d_in[6];
    const float* WihI   = (const float*)d_in[7];
    const float* WhhI   = (const float*)d_in[8];
    const float* bI     = (const float*)d_in[9];
    const float* linW   = (const float*)d_in[10];
    const float* linb   = (const float*)d_in[11];
    float* out = (float*)d_out;
    (void)in_sizes; (void)n_in; (void)out_size;

    cudaFuncSetAttribute(tok_step<true>,  cudaFuncAttributeMaxDynamicSharedMemorySize, SMEM_TOK);
    cudaFuncSetAttribute(tok_step<false>, cudaFuncAttributeMaxDynamicSharedMemorySize, SMEM_TOK);
    cudaFuncSetAttribute(ins_step<true>,  cudaFuncAttributeMaxDynamicSharedMemorySize, SMEM_INS);
    cudaFuncSetAttribute(ins_step<false>, cudaFuncAttributeMaxDynamicSharedMemorySize, SMEM_INS);

    zero_state<<<NTOK * HID / 256, 256>>>();
    build_perm<<<2, 512>>>(ntok, ninstr);
    prep_all<<<4096 * EMB / 256, 256>>>(WihT, WhhT, WihI, WhhI, emb);

    {
        dim3 grid(NTOK / TBM, FOURH / BN);             // 256 x 16, blocks self-trim
        tok_step<true><<<grid, 256, SMEM_TOK>>>(0, blocks, bT, ntok);
        for (int t = 1; t < TOKENS; ++t)
            tok_step<false><<<grid, 256, SMEM_TOK>>>(t, blocks, bT, ntok);
    }
    gather_tok<<<NTOK * HID / 256, 256>>>(ntok);
    {
        dim3 grid(BATCH / IBM, FOURH / IBN);           // 2 x 64
        ins_step<true><<<grid, 256, SMEM_INS>>>(0, bI, ninstr);
        for (int s = 1; s < INSTRS; ++s)
            ins_step<false><<<grid, 256, SMEM_INS>>>(s, bI, ninstr);
    }
    final_linear<<<BATCH, 256>>>(ninstr, linW, linb, out);
}